// round 11
// baseline (speedup 1.0000x reference)
#include <cuda_runtime.h>
#include <math.h>

#define DMODEL 1024
#define NHEAD  16
#define HD     64
#define BATCH  4
#define SEQ    2048
#define MROWS  (BATCH*SEQ)   // 8192

#define A_STRIDE 36     // floats; A-frag LDS banks = 4*qid+tg (conflict-free)
#define W_STRIDE 136    // floats; B-frag LDS banks = 8*tg+qid (conflict-free)

// Scratch (allocation-free rule: __device__ globals)
__device__ float g_h[MROWS*DMODEL];
__device__ float g_q[MROWS*DMODEL];
__device__ float g_k[MROWS*DMODEL];
__device__ float g_v[MROWS*DMODEL];
__device__ float g_attn[MROWS*DMODEL];
// tf32-pre-rounded weights
__device__ float g_wq[DMODEL*DMODEL];
__device__ float g_wk[DMODEL*DMODEL];
__device__ float g_wv[DMODEL*DMODEL];
__device__ float g_wo[DMODEL*DMODEL];

__device__ __forceinline__ float to_tf32(float x) {
    float r;
    asm("cvt.rna.tf32.f32 %0, %1;" : "=f"(r) : "f"(x));
    return r;
}

__device__ __forceinline__ unsigned smem_u32(const void* p) {
    return (unsigned)__cvta_generic_to_shared(p);
}
__device__ __forceinline__ void cp_async16(unsigned saddr, const void* gptr) {
    asm volatile("cp.async.cg.shared.global [%0], [%1], 16;\n" :: "r"(saddr), "l"(gptr));
}

// ---------------- tf32 pre-round (4 weight matrices, one launch) ----------------
__global__ void round_tf32_kernel(const float* __restrict__ s0, float* __restrict__ d0,
                                  const float* __restrict__ s1, float* __restrict__ d1,
                                  const float* __restrict__ s2, float* __restrict__ d2,
                                  const float* __restrict__ s3, float* __restrict__ d3) {
    const float* src; float* dst;
    if (blockIdx.z == 0)      { src = s0; dst = d0; }
    else if (blockIdx.z == 1) { src = s1; dst = d1; }
    else if (blockIdx.z == 2) { src = s2; dst = d2; }
    else                      { src = s3; dst = d3; }
    int i = blockIdx.x * blockDim.x + threadIdx.x;   // float4 index
    float4 v = reinterpret_cast<const float4*>(src)[i];
    v.x = to_tf32(v.x); v.y = to_tf32(v.y);
    v.z = to_tf32(v.z); v.w = to_tf32(v.w);
    reinterpret_cast<float4*>(dst)[i] = v;
}

// ---------------- LayerNorm: one WARP per row (tf32-rounded output) ----------------
// 256 threads = 8 rows per block; no block-level barriers.
__global__ void ln_kernel(const float* __restrict__ x,
                          const float* __restrict__ gamma,
                          const float* __restrict__ beta,
                          float* __restrict__ out) {
    const int lane = threadIdx.x & 31;
    const int row = blockIdx.x * 8 + (threadIdx.x >> 5);
    const float* xr = x + (size_t)row * DMODEL;
    float* orow = out + (size_t)row * DMODEL;

    float4 xv[8];
    float s = 0.f, s2 = 0.f;
    #pragma unroll
    for (int i = 0; i < 8; i++) {
        xv[i] = reinterpret_cast<const float4*>(xr)[lane + i * 32];
        s  += xv[i].x + xv[i].y + xv[i].z + xv[i].w;
        s2 += xv[i].x*xv[i].x + xv[i].y*xv[i].y + xv[i].z*xv[i].z + xv[i].w*xv[i].w;
    }
    #pragma unroll
    for (int o = 16; o; o >>= 1) {
        s  += __shfl_xor_sync(0xffffffffu, s,  o);
        s2 += __shfl_xor_sync(0xffffffffu, s2, o);
    }
    float mean = s * (1.0f / DMODEL);
    float var  = s2 * (1.0f / DMODEL) - mean * mean;
    float rstd = rsqrtf(var + 1e-5f);
    #pragma unroll
    for (int i = 0; i < 8; i++) {
        float4 gv = reinterpret_cast<const float4*>(gamma)[lane + i * 32];
        float4 bv = reinterpret_cast<const float4*>(beta)[lane + i * 32];
        float4 ov;
        ov.x = to_tf32((xv[i].x - mean) * rstd * gv.x + bv.x);
        ov.y = to_tf32((xv[i].y - mean) * rstd * gv.y + bv.y);
        ov.z = to_tf32((xv[i].z - mean) * rstd * gv.z + bv.z);
        ov.w = to_tf32((xv[i].w - mean) * rstd * gv.w + bv.w);
        reinterpret_cast<float4*>(orow)[lane + i * 32] = ov;
    }
}

// ------------- tf32 GEMM 128x128x32, cp.async double-buffered -------------
// C = A@W + bias. Inputs must be tf32-pre-rounded. blockIdx.z selects triple.
// round_out != 0: outputs rounded to tf32 (for q/k/v feeding attention).
__global__ __launch_bounds__(256, 2)
void gemm_bias_kernel(const float* __restrict__ A,
                      const float* __restrict__ W0, const float* __restrict__ bias0, float* __restrict__ C0,
                      const float* __restrict__ W1, const float* __restrict__ bias1, float* __restrict__ C1,
                      const float* __restrict__ W2, const float* __restrict__ bias2, float* __restrict__ C2,
                      int round_out) {
    const float* W; const float* bias; float* C;
    if (blockIdx.z == 0)      { W = W0; bias = bias0; C = C0; }
    else if (blockIdx.z == 1) { W = W1; bias = bias1; C = C1; }
    else                      { W = W2; bias = bias2; C = C2; }

    __shared__ float As[2][128 * A_STRIDE];   // [m][k] + pad
    __shared__ float Ws[2][32 * W_STRIDE];    // [k][n] + pad

    const int tid = threadIdx.x;
    const int bm = blockIdx.y * 128;
    const int bn = blockIdx.x * 128;
    const int lane = tid & 31;
    const int wid  = tid >> 5;
    const int warp_m = wid & 1;      // 2 warps along M
    const int warp_n = wid >> 1;     // 4 warps along N
    const int qid = lane >> 2;       // 0..7
    const int tg  = lane & 3;        // 0..3

    float acc[4][4][4];
    #pragma unroll
    for (int mi = 0; mi < 4; mi++)
        #pragma unroll
        for (int nj = 0; nj < 4; nj++)
            #pragma unroll
            for (int r = 0; r < 4; r++) acc[mi][nj][r] = 0.f;

    // ---- async tile loader ----
    auto issue_tile = [&](int s, int k0) {
        #pragma unroll
        for (int l = 0; l < 4; l++) {
            int f  = tid + l * 256;          // 0..1023
            int m  = f >> 3;                 // 0..127
            int kc = f & 7;                  // 16B chunk within 32 k
            cp_async16(smem_u32(&As[s][m * A_STRIDE + kc * 4]),
                       A + (size_t)(bm + m) * DMODEL + k0 + kc * 4);
        }
        #pragma unroll
        for (int l = 0; l < 4; l++) {
            int f  = tid + l * 256;
            int k  = f >> 5;                 // 0..31
            int nc = f & 31;
            cp_async16(smem_u32(&Ws[s][k * W_STRIDE + nc * 4]),
                       W + (size_t)(k0 + k) * DMODEL + bn + nc * 4);
        }
        asm volatile("cp.async.commit_group;\n");
    };

    issue_tile(0, 0);

    const int NITER = DMODEL / 32;           // 32
    for (int it = 0; it < NITER; it++) {
        const int s = it & 1;
        if (it + 1 < NITER) {
            issue_tile(s ^ 1, (it + 1) * 32);
            asm volatile("cp.async.wait_group 1;\n");
        } else {
            asm volatile("cp.async.wait_group 0;\n");
        }
        __syncthreads();

        const float* Ab = &As[s][(warp_m * 64 + qid) * A_STRIDE];
        const float* Wb = &Ws[s][warp_n * 32 + qid];
        #pragma unroll
        for (int kk = 0; kk < 4; kk++) {
            const int kA0 = kk * 8 + tg;
            const int kA1 = kA0 + 4;
            unsigned a[4][4], b[4][2];
            #pragma unroll
            for (int mi = 0; mi < 4; mi++) {
                a[mi][0] = __float_as_uint(Ab[(mi * 16 + 0) * A_STRIDE + kA0]);
                a[mi][1] = __float_as_uint(Ab[(mi * 16 + 8) * A_STRIDE + kA0]);
                a[mi][2] = __float_as_uint(Ab[(mi * 16 + 0) * A_STRIDE + kA1]);
                a[mi][3] = __float_as_uint(Ab[(mi * 16 + 8) * A_STRIDE + kA1]);
            }
            #pragma unroll
            for (int nj = 0; nj < 4; nj++) {
                b[nj][0] = __float_as_uint(Wb[kA0 * W_STRIDE + nj * 8]);
                b[nj][1] = __float_as_uint(Wb[kA1 * W_STRIDE + nj * 8]);
            }
            #pragma unroll
            for (int mi = 0; mi < 4; mi++)
                #pragma unroll
                for (int nj = 0; nj < 4; nj++) {
                    asm volatile(
                        "mma.sync.aligned.m16n8k8.row.col.f32.tf32.tf32.f32 "
                        "{%0,%1,%2,%3}, {%4,%5,%6,%7}, {%8,%9}, {%0,%1,%2,%3};"
                        : "+f"(acc[mi][nj][0]), "+f"(acc[mi][nj][1]),
                          "+f"(acc[mi][nj][2]), "+f"(acc[mi][nj][3])
                        : "r"(a[mi][0]), "r"(a[mi][1]), "r"(a[mi][2]), "r"(a[mi][3]),
                          "r"(b[nj][0]), "r"(b[nj][1]));
                }
        }
        __syncthreads();
    }

    if (round_out) {
        #pragma unroll
        for (int mi = 0; mi < 4; mi++) {
            int row = bm + warp_m * 64 + mi * 16 + qid;
            #pragma unroll
            for (int nj = 0; nj < 4; nj++) {
                int col = bn + warp_n * 32 + nj * 8 + tg * 2;
                float b0 = bias[col], b1 = bias[col + 1];
                float2 v0 = make_float2(to_tf32(acc[mi][nj][0] + b0), to_tf32(acc[mi][nj][1] + b1));
                float2 v1 = make_float2(to_tf32(acc[mi][nj][2] + b0), to_tf32(acc[mi][nj][3] + b1));
                *reinterpret_cast<float2*>(&C[(size_t)row * DMODEL + col]) = v0;
                *reinterpret_cast<float2*>(&C[(size_t)(row + 8) * DMODEL + col]) = v1;
            }
        }
    } else {
        #pragma unroll
        for (int mi = 0; mi < 4; mi++) {
            int row = bm + warp_m * 64 + mi * 16 + qid;
            #pragma unroll
            for (int nj = 0; nj < 4; nj++) {
                int col = bn + warp_n * 32 + nj * 8 + tg * 2;
                float b0 = bias[col], b1 = bias[col + 1];
                float2 v0 = make_float2(acc[mi][nj][0] + b0, acc[mi][nj][1] + b1);
                float2 v1 = make_float2(acc[mi][nj][2] + b0, acc[mi][nj][3] + b1);
                *reinterpret_cast<float2*>(&C[(size_t)row * DMODEL + col]) = v0;
                *reinterpret_cast<float2*>(&C[(size_t)(row + 8) * DMODEL + col]) = v1;
            }
        }
    }
}

// ------------- tf32 tensor-core causal flash attention, cp.async 2-stage -------------
// CTA: 128 q-rows, 8 warps, each warp owns 16 rows x full 64-key width.
// Q/K/V are tf32-pre-rounded by the QKV GEMM epilogue -> raw cp.async, no cvt.
// Dynamic smem: Ks[2][16*256] + Vs[2][64*72] = 69632 B.
__global__ __launch_bounds__(256, 1)
void attn_tc_kernel(const float* __restrict__ Q, const float* __restrict__ K,
                    const float* __restrict__ V, float* __restrict__ O) {
    extern __shared__ float sm[];
    float* KsBuf[2] = { sm,        sm + 4096 };          // 16 KB each
    float* VsBuf[2] = { sm + 8192, sm + 12800 };         // 18 KB each (stride 72)

    const int qt = blockIdx.x, h = blockIdx.y, b = blockIdx.z;
    const int tid = threadIdx.x;
    const int lane = tid & 31;
    const int w = tid >> 5;
    const int q4 = lane >> 2;        // group id 0..7
    const int r4 = lane & 3;         // thread-in-group 0..3
    const size_t base = (size_t)b * SEQ * DMODEL + (size_t)h * HD;

    const int row0 = qt * 128 + w * 16 + q4;   // this thread's first q row

    // ---- per-thread cp.async indices (hoisted) ----
    const int cn0 = tid >> 4;          // key for f=tid (l=0): 0..15
    const int cd0 = tid & 15;          // dblk for f=tid

    // ---- async K/V tile loader (8x cp.async per thread) ----
    auto issue_kv = [&](int j, int s) {
        const float* Kp = K + base + (size_t)(j * 64) * DMODEL;
        const float* Vp = V + base + (size_t)(j * 64) * DMODEL;
        #pragma unroll
        for (int l = 0; l < 4; l++) {
            int n = cn0 + l * 16;
            int dblk = cd0;
            cp_async16(smem_u32(&KsBuf[s][dblk * 256 + ((n ^ (dblk & 7)) << 2)]),
                       Kp + (size_t)n * DMODEL + dblk * 4);
            cp_async16(smem_u32(&VsBuf[s][n * 72 + dblk * 4]),
                       Vp + (size_t)n * DMODEL + dblk * 4);
        }
        asm volatile("cp.async.commit_group;\n");
    };

    // ---- Q fragments (pre-rounded; pow2 scale exact, no cvt needed) ----
    unsigned qf[8][4];
    {
        const float* Qp = Q + base + (size_t)row0 * DMODEL;
        #pragma unroll
        for (int ks = 0; ks < 8; ks++) {
            qf[ks][0] = __float_as_uint(Qp[ks * 8 + r4] * 0.125f);
            qf[ks][1] = __float_as_uint(Qp[8 * DMODEL + ks * 8 + r4] * 0.125f);
            qf[ks][2] = __float_as_uint(Qp[ks * 8 + r4 + 4] * 0.125f);
            qf[ks][3] = __float_as_uint(Qp[8 * DMODEL + ks * 8 + r4 + 4] * 0.125f);
        }
    }

    float m0 = -1e30f, m1 = -1e30f, l0 = 0.f, l1 = 0.f;
    float oacc[8][4];
    #pragma unroll
    for (int of = 0; of < 8; of++)
        #pragma unroll
        for (int r = 0; r < 4; r++) oacc[of][r] = 0.f;

    const int jmax = 2 * qt + 1;
    issue_kv(0, 0);

    for (int j = 0; j <= jmax; j++) {
        const int s = j & 1;
        if (j < jmax) {
            issue_kv(j + 1, s ^ 1);
            asm volatile("cp.async.wait_group 1;\n");
        } else {
            asm volatile("cp.async.wait_group 0;\n");
        }
        __syncthreads();
        const float* Ks = KsBuf[s];
        const float* Vs = VsBuf[s];

        // ---- S = (Q/8) K^T : 8 n-frags ----
        float sacc[8][4];
        #pragma unroll
        for (int nf = 0; nf < 8; nf++)
            #pragma unroll
            for (int r = 0; r < 4; r++) sacc[nf][r] = 0.f;

        #pragma unroll
        for (int ks = 0; ks < 8; ks++) {
            const int p0 = (2 * ks) * 256 + ((q4 ^ ((2 * ks) & 7)) << 2) + r4;
            const int p1 = (2 * ks + 1) * 256 + ((q4 ^ ((2 * ks + 1) & 7)) << 2) + r4;
            #pragma unroll
            for (int nf = 0; nf < 8; nf++) {
                unsigned b0 = __float_as_uint(Ks[p0 + nf * 32]);
                unsigned b1 = __float_as_uint(Ks[p1 + nf * 32]);
                asm volatile(
                    "mma.sync.aligned.m16n8k8.row.col.f32.tf32.tf32.f32 "
                    "{%0,%1,%2,%3}, {%4,%5,%6,%7}, {%8,%9}, {%0,%1,%2,%3};"
                    : "+f"(sacc[nf][0]), "+f"(sacc[nf][1]),
                      "+f"(sacc[nf][2]), "+f"(sacc[nf][3])
                    : "r"(qf[ks][0]), "r"(qf[ks][1]), "r"(qf[ks][2]), "r"(qf[ks][3]),
                      "r"(b0), "r"(b1));
            }
        }

        // ---- causal mask (only diagonal tiles) ----
        if (j >= 2 * qt) {
            int gcol0 = j * 64 + r4 * 2;
            #pragma unroll
            for (int nf = 0; nf < 8; nf++) {
                int c = gcol0 + nf * 8;
                if (c     > row0)     sacc[nf][0] = -1e30f;
                if (c + 1 > row0)     sacc[nf][1] = -1e30f;
                if (c     > row0 + 8) sacc[nf][2] = -1e30f;
                if (c + 1 > row0 + 8) sacc[nf][3] = -1e30f;
            }
        }

        // ---- online softmax ----
        float rmax0 = -1e30f, rmax1 = -1e30f;
        #pragma unroll
        for (int nf = 0; nf < 8; nf++) {
            rmax0 = fmaxf(rmax0, fmaxf(sacc[nf][0], sacc[nf][1]));
            rmax1 = fmaxf(rmax1, fmaxf(sacc[nf][2], sacc[nf][3]));
        }
        rmax0 = fmaxf(rmax0, __shfl_xor_sync(0xffffffffu, rmax0, 1));
        rmax0 = fmaxf(rmax0, __shfl_xor_sync(0xffffffffu, rmax0, 2));
        rmax1 = fmaxf(rmax1, __shfl_xor_sync(0xffffffffu, rmax1, 1));
        rmax1 = fmaxf(rmax1, __shfl_xor_sync(0xffffffffu, rmax1, 2));
        float mn0 = fmaxf(m0, rmax0), mn1 = fmaxf(m1, rmax1);
        float al0 = __expf(m0 - mn0), al1 = __expf(m1 - mn1);
        m0 = mn0; m1 = mn1;
        float rs0 = 0.f, rs1 = 0.f;
        #pragma unroll
        for (int nf = 0; nf < 8; nf++) {
            sacc[nf][0] = __expf(sacc[nf][0] - mn0);
            sacc[nf][1] = __expf(sacc[nf][1] - mn0);
            sacc[nf][2] = __expf(sacc[nf][2] - mn1);
            sacc[nf][3] = __expf(sacc[nf][3] - mn1);
            rs0 += sacc[nf][0] + sacc[nf][1];
            rs1 += sacc[nf][2] + sacc[nf][3];
        }
        rs0 += __shfl_xor_sync(0xffffffffu, rs0, 1);
        rs0 += __shfl_xor_sync(0xffffffffu, rs0, 2);
        rs1 += __shfl_xor_sync(0xffffffffu, rs1, 1);
        rs1 += __shfl_xor_sync(0xffffffffu, rs1, 2);
        l0 = l0 * al0 + rs0;
        l1 = l1 * al1 + rs1;
        #pragma unroll
        for (int of = 0; of < 8; of++) {
            oacc[of][0] *= al0; oacc[of][1] *= al0;
            oacc[of][2] *= al1; oacc[of][3] *= al1;
        }

        // ---- O += P @ V (P A-frags built via shfl from sacc) ----
        const int srcA = (lane & 28) | (r4 >> 1);
        const int srcB = srcA | 2;
        const bool odd = (r4 & 1);
        #pragma unroll
        for (int ks = 0; ks < 8; ks++) {
            float v0 = __shfl_sync(0xffffffffu, sacc[ks][0], srcA);
            float v1 = __shfl_sync(0xffffffffu, sacc[ks][1], srcA);
            float v2 = __shfl_sync(0xffffffffu, sacc[ks][2], srcA);
            float v3 = __shfl_sync(0xffffffffu, sacc[ks][3], srcA);
            float u0 = __shfl_sync(0xffffffffu, sacc[ks][0], srcB);
            float u1 = __shfl_sync(0xffffffffu, sacc[ks][1], srcB);
            float u2 = __shfl_sync(0xffffffffu, sacc[ks][2], srcB);
            float u3 = __shfl_sync(0xffffffffu, sacc[ks][3], srcB);
            unsigned a0 = __float_as_uint(to_tf32(odd ? v1 : v0));
            unsigned a1 = __float_as_uint(to_tf32(odd ? v3 : v2));
            unsigned a2 = __float_as_uint(to_tf32(odd ? u1 : u0));
            unsigned a3 = __float_as_uint(to_tf32(odd ? u3 : u2));
            const int vb0 = (ks * 8 + r4) * 72 + q4;
            const int vb1 = (ks * 8 + r4 + 4) * 72 + q4;
            #pragma unroll
            for (int of = 0; of < 8; of++) {
                unsigned b0 = __float_as_uint(Vs[vb0 + of * 8]);
                unsigned b1 = __float_as_uint(Vs[vb1 + of * 8]);
                asm volatile(
                    "mma.sync.aligned.m16n8k8.row.col.f32.tf32.tf32.f32 "
                    "{%0,%1,%2,%3}, {%4,%5,%6,%7}, {%8,%9}, {%0,%1,%2,%3};"
                    : "+f"(oacc[of][0]), "+f"(oacc[of][1]),
                      "+f"(oacc[of][2]), "+f"(oacc[of][3])
                    : "r"(a0), "r"(a1), "r"(a2), "r"(a3),
                      "r"(b0), "r"(b1));
            }
        }
        __syncthreads();
    }

    // ---- epilogue (tf32-rounded for the Wo GEMM) ----
    float inv0 = 1.0f / l0, inv1 = 1.0f / l1;
    #pragma unroll
    for (int of = 0; of < 8; of++) {
        int col = of * 8 + r4 * 2;
        float2 w0 = make_float2(to_tf32(oacc[of][0] * inv0), to_tf32(oacc[of][1] * inv0));
        float2 w1 = make_float2(to_tf32(oacc[of][2] * inv1), to_tf32(oacc[of][3] * inv1));
        *reinterpret_cast<float2*>(&O[base + (size_t)row0 * DMODEL + col]) = w0;
        *reinterpret_cast<float2*>(&O[base + (size_t)(row0 + 8) * DMODEL + col]) = w1;
    }
}

extern "C" void kernel_launch(void* const* d_in, const int* in_sizes, int n_in,
                              void* d_out, int out_size) {
    (void)in_sizes; (void)n_in; (void)out_size;
    const float* x     = (const float*)d_in[0];
    const float* Wq    = (const float*)d_in[1];
    const float* bq    = (const float*)d_in[2];
    const float* Wk    = (const float*)d_in[3];
    const float* bk    = (const float*)d_in[4];
    const float* Wv    = (const float*)d_in[5];
    const float* bv    = (const float*)d_in[6];
    const float* Wo    = (const float*)d_in[7];
    const float* bo    = (const float*)d_in[8];
    const float* gamma = (const float*)d_in[9];
    const float* beta  = (const float*)d_in[10];
    float* out = (float*)d_out;

    float *h, *q, *k, *v, *attn, *wq, *wk, *wv, *wo;
    cudaGetSymbolAddress((void**)&h,    g_h);
    cudaGetSymbolAddress((void**)&q,    g_q);
    cudaGetSymbolAddress((void**)&k,    g_k);
    cudaGetSymbolAddress((void**)&v,    g_v);
    cudaGetSymbolAddress((void**)&attn, g_attn);
    cudaGetSymbolAddress((void**)&wq,   g_wq);
    cudaGetSymbolAddress((void**)&wk,   g_wk);
    cudaGetSymbolAddress((void**)&wv,   g_wv);
    cudaGetSymbolAddress((void**)&wo,   g_wo);

    // pre-round weights to tf32 (rna) in one launch
    dim3 rgrid((DMODEL * DMODEL / 4) / 256, 1, 4);
    round_tf32_kernel<<<rgrid, 256>>>(Wq, wq, Wk, wk, Wv, wv, Wo, wo);

    ln_kernel<<<MROWS / 8, 256>>>(x, gamma, beta, h);

    // fused QKV projection: one launch, z selects (W, bias, C); outputs tf32-rounded
    dim3 gqkv(DMODEL / 128, MROWS / 128, 3);   // (8, 64, 3)
    gemm_bias_kernel<<<gqkv, 256>>>(h, wq, bq, q, wk, bk, k, wv, bv, v, 1);

    int asmem = 69632;
    cudaFuncSetAttribute(attn_tc_kernel, cudaFuncAttributeMaxDynamicSharedMemorySize, asmem);
    attn_tc_kernel<<<dim3(SEQ / 128, NHEAD, BATCH), 256, asmem>>>(q, k, v, attn);

    dim3 go(DMODEL / 128, MROWS / 128, 1);
    gemm_bias_kernel<<<go, 256>>>(attn, wo, bo, out, wo, bo, out, wo, bo, out, 0);
}

// round 14
// speedup vs baseline: 1.1182x; 1.1182x over previous
#include <cuda_runtime.h>
#include <math.h>

#define DMODEL 1024
#define NHEAD  16
#define HD     64
#define BATCH  4
#define SEQ    2048
#define MROWS  (BATCH*SEQ)   // 8192

#define A_STRIDE 36     // floats; A-frag LDS banks = 4*qid+tg (conflict-free)
#define W_STRIDE 136    // floats; B-frag LDS banks = 8*tg+qid (conflict-free)

// Scratch (allocation-free rule: __device__ globals)
__device__ float g_h[MROWS*DMODEL];
__device__ float g_q[MROWS*DMODEL];
__device__ float g_k[MROWS*DMODEL];
__device__ float g_v[MROWS*DMODEL];
__device__ float g_attn[MROWS*DMODEL];
// tf32-pre-rounded weights
__device__ float g_wq[DMODEL*DMODEL];
__device__ float g_wk[DMODEL*DMODEL];
__device__ float g_wv[DMODEL*DMODEL];
__device__ float g_wo[DMODEL*DMODEL];

__device__ __forceinline__ float to_tf32(float x) {
    float r;
    asm("cvt.rna.tf32.f32 %0, %1;" : "=f"(r) : "f"(x));
    return r;
}

__device__ __forceinline__ unsigned smem_u32(const void* p) {
    return (unsigned)__cvta_generic_to_shared(p);
}
__device__ __forceinline__ void cp_async16(unsigned saddr, const void* gptr) {
    asm volatile("cp.async.cg.shared.global [%0], [%1], 16;\n" :: "r"(saddr), "l"(gptr));
}

// ---------------- tf32 pre-round (4 weight matrices, one launch) ----------------
__global__ void round_tf32_kernel(const float* __restrict__ s0, float* __restrict__ d0,
                                  const float* __restrict__ s1, float* __restrict__ d1,
                                  const float* __restrict__ s2, float* __restrict__ d2,
                                  const float* __restrict__ s3, float* __restrict__ d3) {
    const float* src; float* dst;
    if (blockIdx.z == 0)      { src = s0; dst = d0; }
    else if (blockIdx.z == 1) { src = s1; dst = d1; }
    else if (blockIdx.z == 2) { src = s2; dst = d2; }
    else                      { src = s3; dst = d3; }
    int i = blockIdx.x * blockDim.x + threadIdx.x;   // float4 index
    float4 v = reinterpret_cast<const float4*>(src)[i];
    v.x = to_tf32(v.x); v.y = to_tf32(v.y);
    v.z = to_tf32(v.z); v.w = to_tf32(v.w);
    reinterpret_cast<float4*>(dst)[i] = v;
}

// ---------------- LayerNorm: one WARP per row (tf32-rounded output) ----------------
__global__ void ln_kernel(const float* __restrict__ x,
                          const float* __restrict__ gamma,
                          const float* __restrict__ beta,
                          float* __restrict__ out) {
    const int lane = threadIdx.x & 31;
    const int row = blockIdx.x * 8 + (threadIdx.x >> 5);
    const float* xr = x + (size_t)row * DMODEL;
    float* orow = out + (size_t)row * DMODEL;

    float4 xv[8];
    float s = 0.f, s2 = 0.f;
    #pragma unroll
    for (int i = 0; i < 8; i++) {
        xv[i] = reinterpret_cast<const float4*>(xr)[lane + i * 32];
        s  += xv[i].x + xv[i].y + xv[i].z + xv[i].w;
        s2 += xv[i].x*xv[i].x + xv[i].y*xv[i].y + xv[i].z*xv[i].z + xv[i].w*xv[i].w;
    }
    #pragma unroll
    for (int o = 16; o; o >>= 1) {
        s  += __shfl_xor_sync(0xffffffffu, s,  o);
        s2 += __shfl_xor_sync(0xffffffffu, s2, o);
    }
    float mean = s * (1.0f / DMODEL);
    float var  = s2 * (1.0f / DMODEL) - mean * mean;
    float rstd = rsqrtf(var + 1e-5f);
    #pragma unroll
    for (int i = 0; i < 8; i++) {
        float4 gv = reinterpret_cast<const float4*>(gamma)[lane + i * 32];
        float4 bv = reinterpret_cast<const float4*>(beta)[lane + i * 32];
        float4 ov;
        ov.x = to_tf32((xv[i].x - mean) * rstd * gv.x + bv.x);
        ov.y = to_tf32((xv[i].y - mean) * rstd * gv.y + bv.y);
        ov.z = to_tf32((xv[i].z - mean) * rstd * gv.z + bv.z);
        ov.w = to_tf32((xv[i].w - mean) * rstd * gv.w + bv.w);
        reinterpret_cast<float4*>(orow)[lane + i * 32] = ov;
    }
}

// ------------- tf32 GEMM 128x128x32, cp.async double-buffered -------------
__global__ __launch_bounds__(256, 2)
void gemm_bias_kernel(const float* __restrict__ A,
                      const float* __restrict__ W0, const float* __restrict__ bias0, float* __restrict__ C0,
                      const float* __restrict__ W1, const float* __restrict__ bias1, float* __restrict__ C1,
                      const float* __restrict__ W2, const float* __restrict__ bias2, float* __restrict__ C2,
                      int round_out) {
    const float* W; const float* bias; float* C;
    if (blockIdx.z == 0)      { W = W0; bias = bias0; C = C0; }
    else if (blockIdx.z == 1) { W = W1; bias = bias1; C = C1; }
    else                      { W = W2; bias = bias2; C = C2; }

    __shared__ float As[2][128 * A_STRIDE];   // [m][k] + pad
    __shared__ float Ws[2][32 * W_STRIDE];    // [k][n] + pad

    const int tid = threadIdx.x;
    const int bm = blockIdx.y * 128;
    const int bn = blockIdx.x * 128;
    const int lane = tid & 31;
    const int wid  = tid >> 5;
    const int warp_m = wid & 1;      // 2 warps along M
    const int warp_n = wid >> 1;     // 4 warps along N
    const int qid = lane >> 2;       // 0..7
    const int tg  = lane & 3;        // 0..3

    float acc[4][4][4];
    #pragma unroll
    for (int mi = 0; mi < 4; mi++)
        #pragma unroll
        for (int nj = 0; nj < 4; nj++)
            #pragma unroll
            for (int r = 0; r < 4; r++) acc[mi][nj][r] = 0.f;

    auto issue_tile = [&](int s, int k0) {
        #pragma unroll
        for (int l = 0; l < 4; l++) {
            int f  = tid + l * 256;          // 0..1023
            int m  = f >> 3;                 // 0..127
            int kc = f & 7;                  // 16B chunk within 32 k
            cp_async16(smem_u32(&As[s][m * A_STRIDE + kc * 4]),
                       A + (size_t)(bm + m) * DMODEL + k0 + kc * 4);
        }
        #pragma unroll
        for (int l = 0; l < 4; l++) {
            int f  = tid + l * 256;
            int k  = f >> 5;                 // 0..31
            int nc = f & 31;
            cp_async16(smem_u32(&Ws[s][k * W_STRIDE + nc * 4]),
                       W + (size_t)(k0 + k) * DMODEL + bn + nc * 4);
        }
        asm volatile("cp.async.commit_group;\n");
    };

    issue_tile(0, 0);

    const int NITER = DMODEL / 32;           // 32
    for (int it = 0; it < NITER; it++) {
        const int s = it & 1;
        if (it + 1 < NITER) {
            issue_tile(s ^ 1, (it + 1) * 32);
            asm volatile("cp.async.wait_group 1;\n");
        } else {
            asm volatile("cp.async.wait_group 0;\n");
        }
        __syncthreads();

        const float* Ab = &As[s][(warp_m * 64 + qid) * A_STRIDE];
        const float* Wb = &Ws[s][warp_n * 32 + qid];
        #pragma unroll
        for (int kk = 0; kk < 4; kk++) {
            const int kA0 = kk * 8 + tg;
            const int kA1 = kA0 + 4;
            unsigned a[4][4], b[4][2];
            #pragma unroll
            for (int mi = 0; mi < 4; mi++) {
                a[mi][0] = __float_as_uint(Ab[(mi * 16 + 0) * A_STRIDE + kA0]);
                a[mi][1] = __float_as_uint(Ab[(mi * 16 + 8) * A_STRIDE + kA0]);
                a[mi][2] = __float_as_uint(Ab[(mi * 16 + 0) * A_STRIDE + kA1]);
                a[mi][3] = __float_as_uint(Ab[(mi * 16 + 8) * A_STRIDE + kA1]);
            }
            #pragma unroll
            for (int nj = 0; nj < 4; nj++) {
                b[nj][0] = __float_as_uint(Wb[kA0 * W_STRIDE + nj * 8]);
                b[nj][1] = __float_as_uint(Wb[kA1 * W_STRIDE + nj * 8]);
            }
            #pragma unroll
            for (int mi = 0; mi < 4; mi++)
                #pragma unroll
                for (int nj = 0; nj < 4; nj++) {
                    asm volatile(
                        "mma.sync.aligned.m16n8k8.row.col.f32.tf32.tf32.f32 "
                        "{%0,%1,%2,%3}, {%4,%5,%6,%7}, {%8,%9}, {%0,%1,%2,%3};"
                        : "+f"(acc[mi][nj][0]), "+f"(acc[mi][nj][1]),
                          "+f"(acc[mi][nj][2]), "+f"(acc[mi][nj][3])
                        : "r"(a[mi][0]), "r"(a[mi][1]), "r"(a[mi][2]), "r"(a[mi][3]),
                          "r"(b[nj][0]), "r"(b[nj][1]));
                }
        }
        __syncthreads();
    }

    if (round_out) {
        #pragma unroll
        for (int mi = 0; mi < 4; mi++) {
            int row = bm + warp_m * 64 + mi * 16 + qid;
            #pragma unroll
            for (int nj = 0; nj < 4; nj++) {
                int col = bn + warp_n * 32 + nj * 8 + tg * 2;
                float b0 = bias[col], b1 = bias[col + 1];
                float2 v0 = make_float2(to_tf32(acc[mi][nj][0] + b0), to_tf32(acc[mi][nj][1] + b1));
                float2 v1 = make_float2(to_tf32(acc[mi][nj][2] + b0), to_tf32(acc[mi][nj][3] + b1));
                *reinterpret_cast<float2*>(&C[(size_t)row * DMODEL + col]) = v0;
                *reinterpret_cast<float2*>(&C[(size_t)(row + 8) * DMODEL + col]) = v1;
            }
        }
    } else {
        #pragma unroll
        for (int mi = 0; mi < 4; mi++) {
            int row = bm + warp_m * 64 + mi * 16 + qid;
            #pragma unroll
            for (int nj = 0; nj < 4; nj++) {
                int col = bn + warp_n * 32 + nj * 8 + tg * 2;
                float b0 = bias[col], b1 = bias[col + 1];
                float2 v0 = make_float2(acc[mi][nj][0] + b0, acc[mi][nj][1] + b1);
                float2 v1 = make_float2(acc[mi][nj][2] + b0, acc[mi][nj][3] + b1);
                *reinterpret_cast<float2*>(&C[(size_t)row * DMODEL + col]) = v0;
                *reinterpret_cast<float2*>(&C[(size_t)(row + 8) * DMODEL + col]) = v1;
            }
        }
    }
}

// ------------- tf32 tensor-core causal flash attention -------------
// CTA: 128 q-rows, 8 warps, each warp owns 16 rows x full 64-key width.
// Q/K/V tf32-pre-rounded by QKV GEMM epilogue -> no cvt on loads.
// Heavy tiles first: qt = gridDim.x-1-blockIdx.x (causal load-balance).
__global__ __launch_bounds__(256, 1)
void attn_tc_kernel(const float* __restrict__ Q, const float* __restrict__ K,
                    const float* __restrict__ V, float* __restrict__ O) {
    __shared__ float Ks[16 * 256];   // 16KB
    __shared__ float Vs[64 * 72];    // 18KB
    const int qt = gridDim.x - 1 - blockIdx.x;   // heavy tiles scheduled first
    const int h = blockIdx.y, b = blockIdx.z;
    const int tid = threadIdx.x;
    const int lane = tid & 31;
    const int w = tid >> 5;
    const int q4 = lane >> 2;        // group id 0..7
    const int r4 = lane & 3;         // thread-in-group 0..3
    const size_t base = (size_t)b * SEQ * DMODEL + (size_t)h * HD;

    const int row0 = qt * 128 + w * 16 + q4;   // this thread's first q row

    // ---- Q fragments (pre-rounded tf32; pow2 scale exact) ----
    unsigned qf[8][4];
    {
        const float* Qp = Q + base + (size_t)row0 * DMODEL;
        #pragma unroll
        for (int ks = 0; ks < 8; ks++) {
            qf[ks][0] = __float_as_uint(Qp[ks * 8 + r4] * 0.125f);
            qf[ks][1] = __float_as_uint(Qp[8 * DMODEL + ks * 8 + r4] * 0.125f);
            qf[ks][2] = __float_as_uint(Qp[ks * 8 + r4 + 4] * 0.125f);
            qf[ks][3] = __float_as_uint(Qp[8 * DMODEL + ks * 8 + r4 + 4] * 0.125f);
        }
    }

    float m0 = -1e30f, m1 = -1e30f, l0 = 0.f, l1 = 0.f;
    float oacc[8][4];
    #pragma unroll
    for (int of = 0; of < 8; of++)
        #pragma unroll
        for (int r = 0; r < 4; r++) oacc[of][r] = 0.f;

    const int jmax = 2 * qt + 1;
    for (int j = 0; j <= jmax; j++) {
        __syncthreads();
        // ---- load K (transposed, swizzled) and V tiles (no cvt; pre-rounded) ----
        #pragma unroll
        for (int l = 0; l < 4; l++) {
            int f = tid + l * 256;          // 0..1023
            int n = f >> 4;                 // key 0..63
            int dblk = f & 15;              // d/4 block
            float4 kv = *reinterpret_cast<const float4*>(
                K + base + (size_t)(j * 64 + n) * DMODEL + dblk * 4);
            *reinterpret_cast<float4*>(&Ks[dblk * 256 + ((n ^ (dblk & 7)) << 2)]) = kv;

            float4 vv = *reinterpret_cast<const float4*>(
                V + base + (size_t)(j * 64 + n) * DMODEL + dblk * 4);
            *reinterpret_cast<float4*>(&Vs[n * 72 + dblk * 4]) = vv;
        }
        __syncthreads();

        // ---- S = (Q/8) K^T : 8 n-frags ----
        float sacc[8][4];
        #pragma unroll
        for (int nf = 0; nf < 8; nf++)
            #pragma unroll
            for (int r = 0; r < 4; r++) sacc[nf][r] = 0.f;

        #pragma unroll
        for (int ks = 0; ks < 8; ks++) {
            const int p0 = (2 * ks) * 256 + ((q4 ^ ((2 * ks) & 7)) << 2) + r4;
            const int p1 = (2 * ks + 1) * 256 + ((q4 ^ ((2 * ks + 1) & 7)) << 2) + r4;
            #pragma unroll
            for (int nf = 0; nf < 8; nf++) {
                unsigned b0 = __float_as_uint(Ks[p0 + nf * 32]);
                unsigned b1 = __float_as_uint(Ks[p1 + nf * 32]);
                asm volatile(
                    "mma.sync.aligned.m16n8k8.row.col.f32.tf32.tf32.f32 "
                    "{%0,%1,%2,%3}, {%4,%5,%6,%7}, {%8,%9}, {%0,%1,%2,%3};"
                    : "+f"(sacc[nf][0]), "+f"(sacc[nf][1]),
                      "+f"(sacc[nf][2]), "+f"(sacc[nf][3])
                    : "r"(qf[ks][0]), "r"(qf[ks][1]), "r"(qf[ks][2]), "r"(qf[ks][3]),
                      "r"(b0), "r"(b1));
            }
        }

        // ---- causal mask (only diagonal tiles) ----
        if (j >= 2 * qt) {
            int gcol0 = j * 64 + r4 * 2;
            #pragma unroll
            for (int nf = 0; nf < 8; nf++) {
                int c = gcol0 + nf * 8;
                if (c     > row0)     sacc[nf][0] = -1e30f;
                if (c + 1 > row0)     sacc[nf][1] = -1e30f;
                if (c     > row0 + 8) sacc[nf][2] = -1e30f;
                if (c + 1 > row0 + 8) sacc[nf][3] = -1e30f;
            }
        }

        // ---- online softmax ----
        float rmax0 = -1e30f, rmax1 = -1e30f;
        #pragma unroll
        for (int nf = 0; nf < 8; nf++) {
            rmax0 = fmaxf(rmax0, fmaxf(sacc[nf][0], sacc[nf][1]));
            rmax1 = fmaxf(rmax1, fmaxf(sacc[nf][2], sacc[nf][3]));
        }
        rmax0 = fmaxf(rmax0, __shfl_xor_sync(0xffffffffu, rmax0, 1));
        rmax0 = fmaxf(rmax0, __shfl_xor_sync(0xffffffffu, rmax0, 2));
        rmax1 = fmaxf(rmax1, __shfl_xor_sync(0xffffffffu, rmax1, 1));
        rmax1 = fmaxf(rmax1, __shfl_xor_sync(0xffffffffu, rmax1, 2));
        float mn0 = fmaxf(m0, rmax0), mn1 = fmaxf(m1, rmax1);
        float al0 = __expf(m0 - mn0), al1 = __expf(m1 - mn1);
        m0 = mn0; m1 = mn1;
        float rs0 = 0.f, rs1 = 0.f;
        #pragma unroll
        for (int nf = 0; nf < 8; nf++) {
            sacc[nf][0] = __expf(sacc[nf][0] - mn0);
            sacc[nf][1] = __expf(sacc[nf][1] - mn0);
            sacc[nf][2] = __expf(sacc[nf][2] - mn1);
            sacc[nf][3] = __expf(sacc[nf][3] - mn1);
            rs0 += sacc[nf][0] + sacc[nf][1];
            rs1 += sacc[nf][2] + sacc[nf][3];
        }
        rs0 += __shfl_xor_sync(0xffffffffu, rs0, 1);
        rs0 += __shfl_xor_sync(0xffffffffu, rs0, 2);
        rs1 += __shfl_xor_sync(0xffffffffu, rs1, 1);
        rs1 += __shfl_xor_sync(0xffffffffu, rs1, 2);
        l0 = l0 * al0 + rs0;
        l1 = l1 * al1 + rs1;
        #pragma unroll
        for (int of = 0; of < 8; of++) {
            oacc[of][0] *= al0; oacc[of][1] *= al0;
            oacc[of][2] *= al1; oacc[of][3] *= al1;
        }

        // ---- O += P @ V (P A-frags built via shfl from sacc) ----
        const int srcA = (lane & 28) | (r4 >> 1);
        const int srcB = srcA | 2;
        const bool odd = (r4 & 1);
        #pragma unroll
        for (int ks = 0; ks < 8; ks++) {
            float v0 = __shfl_sync(0xffffffffu, sacc[ks][0], srcA);
            float v1 = __shfl_sync(0xffffffffu, sacc[ks][1], srcA);
            float v2 = __shfl_sync(0xffffffffu, sacc[ks][2], srcA);
            float v3 = __shfl_sync(0xffffffffu, sacc[ks][3], srcA);
            float u0 = __shfl_sync(0xffffffffu, sacc[ks][0], srcB);
            float u1 = __shfl_sync(0xffffffffu, sacc[ks][1], srcB);
            float u2 = __shfl_sync(0xffffffffu, sacc[ks][2], srcB);
            float u3 = __shfl_sync(0xffffffffu, sacc[ks][3], srcB);
            unsigned a0 = __float_as_uint(to_tf32(odd ? v1 : v0));
            unsigned a1 = __float_as_uint(to_tf32(odd ? v3 : v2));
            unsigned a2 = __float_as_uint(to_tf32(odd ? u1 : u0));
            unsigned a3 = __float_as_uint(to_tf32(odd ? u3 : u2));
            const int vb0 = (ks * 8 + r4) * 72 + q4;
            const int vb1 = (ks * 8 + r4 + 4) * 72 + q4;
            #pragma unroll
            for (int of = 0; of < 8; of++) {
                unsigned b0 = __float_as_uint(Vs[vb0 + of * 8]);
                unsigned b1 = __float_as_uint(Vs[vb1 + of * 8]);
                asm volatile(
                    "mma.sync.aligned.m16n8k8.row.col.f32.tf32.tf32.f32 "
                    "{%0,%1,%2,%3}, {%4,%5,%6,%7}, {%8,%9}, {%0,%1,%2,%3};"
                    : "+f"(oacc[of][0]), "+f"(oacc[of][1]),
                      "+f"(oacc[of][2]), "+f"(oacc[of][3])
                    : "r"(a0), "r"(a1), "r"(a2), "r"(a3),
                      "r"(b0), "r"(b1));
            }
        }
    }

    // ---- epilogue (tf32-rounded for the Wo GEMM) ----
    float inv0 = 1.0f / l0, inv1 = 1.0f / l1;
    #pragma unroll
    for (int of = 0; of < 8; of++) {
        int col = of * 8 + r4 * 2;
        float2 w0 = make_float2(to_tf32(oacc[of][0] * inv0), to_tf32(oacc[of][1] * inv0));
        float2 w1 = make_float2(to_tf32(oacc[of][2] * inv1), to_tf32(oacc[of][3] * inv1));
        *reinterpret_cast<float2*>(&O[base + (size_t)row0 * DMODEL + col]) = w0;
        *reinterpret_cast<float2*>(&O[base + (size_t)(row0 + 8) * DMODEL + col]) = w1;
    }
}

extern "C" void kernel_launch(void* const* d_in, const int* in_sizes, int n_in,
                              void* d_out, int out_size) {
    (void)in_sizes; (void)n_in; (void)out_size;
    const float* x     = (const float*)d_in[0];
    const float* Wq    = (const float*)d_in[1];
    const float* bq    = (const float*)d_in[2];
    const float* Wk    = (const float*)d_in[3];
    const float* bk    = (const float*)d_in[4];
    const float* Wv    = (const float*)d_in[5];
    const float* bv    = (const float*)d_in[6];
    const float* Wo    = (const float*)d_in[7];
    const float* bo    = (const float*)d_in[8];
    const float* gamma = (const float*)d_in[9];
    const float* beta  = (const float*)d_in[10];
    float* out = (float*)d_out;

    float *h, *q, *k, *v, *attn, *wq, *wk, *wv, *wo;
    cudaGetSymbolAddress((void**)&h,    g_h);
    cudaGetSymbolAddress((void**)&q,    g_q);
    cudaGetSymbolAddress((void**)&k,    g_k);
    cudaGetSymbolAddress((void**)&v,    g_v);
    cudaGetSymbolAddress((void**)&attn, g_attn);
    cudaGetSymbolAddress((void**)&wq,   g_wq);
    cudaGetSymbolAddress((void**)&wk,   g_wk);
    cudaGetSymbolAddress((void**)&wv,   g_wv);
    cudaGetSymbolAddress((void**)&wo,   g_wo);

    // pre-round weights to tf32 (rna) in one launch
    dim3 rgrid((DMODEL * DMODEL / 4) / 256, 1, 4);
    round_tf32_kernel<<<rgrid, 256>>>(Wq, wq, Wk, wk, Wv, wv, Wo, wo);

    ln_kernel<<<MROWS / 8, 256>>>(x, gamma, beta, h);

    // fused QKV projection: one launch, z selects (W, bias, C); outputs tf32-rounded
    dim3 gqkv(DMODEL / 128, MROWS / 128, 3);   // (8, 64, 3)
    gemm_bias_kernel<<<gqkv, 256>>>(h, wq, bq, q, wk, bk, k, wv, bv, v, 1);

    attn_tc_kernel<<<dim3(SEQ / 128, NHEAD, BATCH), 256>>>(q, k, v, attn);

    dim3 go(DMODEL / 128, MROWS / 128, 1);
    gemm_bias_kernel<<<go, 256>>>(attn, wo, bo, out, wo, bo, out, wo, bo, out, 0);
}

// round 15
// speedup vs baseline: 1.1831x; 1.0580x over previous
#include <cuda_runtime.h>
#include <math.h>

#define DMODEL 1024
#define NHEAD  16
#define HD     64
#define BATCH  4
#define SEQ    2048
#define MROWS  (BATCH*SEQ)   // 8192

#define A_STRIDE 36     // floats; A-frag LDS banks = 4*qid+tg (conflict-free)
#define W_STRIDE 136    // floats; B-frag LDS banks = 8*tg+qid (conflict-free)

// Scratch (allocation-free rule: __device__ globals)
__device__ float g_h[MROWS*DMODEL];
__device__ float g_q[MROWS*DMODEL];
__device__ float g_k[MROWS*DMODEL];
__device__ float g_v[MROWS*DMODEL];
__device__ float g_attn[MROWS*DMODEL];
// tf32-pre-rounded weights
__device__ float g_wq[DMODEL*DMODEL];
__device__ float g_wk[DMODEL*DMODEL];
__device__ float g_wv[DMODEL*DMODEL];
__device__ float g_wo[DMODEL*DMODEL];

__device__ __forceinline__ float to_tf32(float x) {
    float r;
    asm("cvt.rna.tf32.f32 %0, %1;" : "=f"(r) : "f"(x));
    return r;
}

__device__ __forceinline__ unsigned smem_u32(const void* p) {
    return (unsigned)__cvta_generic_to_shared(p);
}
__device__ __forceinline__ void cp_async16(unsigned saddr, const void* gptr) {
    asm volatile("cp.async.cg.shared.global [%0], [%1], 16;\n" :: "r"(saddr), "l"(gptr));
}

// ---------------- tf32 pre-round (4 weight matrices, one launch) ----------------
__global__ void round_tf32_kernel(const float* __restrict__ s0, float* __restrict__ d0,
                                  const float* __restrict__ s1, float* __restrict__ d1,
                                  const float* __restrict__ s2, float* __restrict__ d2,
                                  const float* __restrict__ s3, float* __restrict__ d3) {
    const float* src; float* dst;
    if (blockIdx.z == 0)      { src = s0; dst = d0; }
    else if (blockIdx.z == 1) { src = s1; dst = d1; }
    else if (blockIdx.z == 2) { src = s2; dst = d2; }
    else                      { src = s3; dst = d3; }
    int i = blockIdx.x * blockDim.x + threadIdx.x;   // float4 index
    float4 v = reinterpret_cast<const float4*>(src)[i];
    v.x = to_tf32(v.x); v.y = to_tf32(v.y);
    v.z = to_tf32(v.z); v.w = to_tf32(v.w);
    reinterpret_cast<float4*>(dst)[i] = v;
}

// ---------------- LayerNorm: one WARP per row (tf32-rounded output) ----------------
__global__ void ln_kernel(const float* __restrict__ x,
                          const float* __restrict__ gamma,
                          const float* __restrict__ beta,
                          float* __restrict__ out) {
    const int lane = threadIdx.x & 31;
    const int row = blockIdx.x * 8 + (threadIdx.x >> 5);
    const float* xr = x + (size_t)row * DMODEL;
    float* orow = out + (size_t)row * DMODEL;

    float4 xv[8];
    float s = 0.f, s2 = 0.f;
    #pragma unroll
    for (int i = 0; i < 8; i++) {
        xv[i] = reinterpret_cast<const float4*>(xr)[lane + i * 32];
        s  += xv[i].x + xv[i].y + xv[i].z + xv[i].w;
        s2 += xv[i].x*xv[i].x + xv[i].y*xv[i].y + xv[i].z*xv[i].z + xv[i].w*xv[i].w;
    }
    #pragma unroll
    for (int o = 16; o; o >>= 1) {
        s  += __shfl_xor_sync(0xffffffffu, s,  o);
        s2 += __shfl_xor_sync(0xffffffffu, s2, o);
    }
    float mean = s * (1.0f / DMODEL);
    float var  = s2 * (1.0f / DMODEL) - mean * mean;
    float rstd = rsqrtf(var + 1e-5f);
    #pragma unroll
    for (int i = 0; i < 8; i++) {
        float4 gv = reinterpret_cast<const float4*>(gamma)[lane + i * 32];
        float4 bv = reinterpret_cast<const float4*>(beta)[lane + i * 32];
        float4 ov;
        ov.x = to_tf32((xv[i].x - mean) * rstd * gv.x + bv.x);
        ov.y = to_tf32((xv[i].y - mean) * rstd * gv.y + bv.y);
        ov.z = to_tf32((xv[i].z - mean) * rstd * gv.z + bv.z);
        ov.w = to_tf32((xv[i].w - mean) * rstd * gv.w + bv.w);
        reinterpret_cast<float4*>(orow)[lane + i * 32] = ov;
    }
}

// ------------- tf32 GEMM 128x128x32, cp.async double-buffered -------------
__global__ __launch_bounds__(256, 2)
void gemm_bias_kernel(const float* __restrict__ A,
                      const float* __restrict__ W0, const float* __restrict__ bias0, float* __restrict__ C0,
                      const float* __restrict__ W1, const float* __restrict__ bias1, float* __restrict__ C1,
                      const float* __restrict__ W2, const float* __restrict__ bias2, float* __restrict__ C2,
                      int round_out) {
    const float* W; const float* bias; float* C;
    if (blockIdx.z == 0)      { W = W0; bias = bias0; C = C0; }
    else if (blockIdx.z == 1) { W = W1; bias = bias1; C = C1; }
    else                      { W = W2; bias = bias2; C = C2; }

    __shared__ float As[2][128 * A_STRIDE];   // [m][k] + pad
    __shared__ float Ws[2][32 * W_STRIDE];    // [k][n] + pad

    const int tid = threadIdx.x;
    const int bm = blockIdx.y * 128;
    const int bn = blockIdx.x * 128;
    const int lane = tid & 31;
    const int wid  = tid >> 5;
    const int warp_m = wid & 1;      // 2 warps along M
    const int warp_n = wid >> 1;     // 4 warps along N
    const int qid = lane >> 2;       // 0..7
    const int tg  = lane & 3;        // 0..3

    float acc[4][4][4];
    #pragma unroll
    for (int mi = 0; mi < 4; mi++)
        #pragma unroll
        for (int nj = 0; nj < 4; nj++)
            #pragma unroll
            for (int r = 0; r < 4; r++) acc[mi][nj][r] = 0.f;

    auto issue_tile = [&](int s, int k0) {
        #pragma unroll
        for (int l = 0; l < 4; l++) {
            int f  = tid + l * 256;          // 0..1023
            int m  = f >> 3;                 // 0..127
            int kc = f & 7;                  // 16B chunk within 32 k
            cp_async16(smem_u32(&As[s][m * A_STRIDE + kc * 4]),
                       A + (size_t)(bm + m) * DMODEL + k0 + kc * 4);
        }
        #pragma unroll
        for (int l = 0; l < 4; l++) {
            int f  = tid + l * 256;
            int k  = f >> 5;                 // 0..31
            int nc = f & 31;
            cp_async16(smem_u32(&Ws[s][k * W_STRIDE + nc * 4]),
                       W + (size_t)(k0 + k) * DMODEL + bn + nc * 4);
        }
        asm volatile("cp.async.commit_group;\n");
    };

    issue_tile(0, 0);

    const int NITER = DMODEL / 32;           // 32
    for (int it = 0; it < NITER; it++) {
        const int s = it & 1;
        if (it + 1 < NITER) {
            issue_tile(s ^ 1, (it + 1) * 32);
            asm volatile("cp.async.wait_group 1;\n");
        } else {
            asm volatile("cp.async.wait_group 0;\n");
        }
        __syncthreads();

        const float* Ab = &As[s][(warp_m * 64 + qid) * A_STRIDE];
        const float* Wb = &Ws[s][warp_n * 32 + qid];
        #pragma unroll
        for (int kk = 0; kk < 4; kk++) {
            const int kA0 = kk * 8 + tg;
            const int kA1 = kA0 + 4;
            unsigned a[4][4], b[4][2];
            #pragma unroll
            for (int mi = 0; mi < 4; mi++) {
                a[mi][0] = __float_as_uint(Ab[(mi * 16 + 0) * A_STRIDE + kA0]);
                a[mi][1] = __float_as_uint(Ab[(mi * 16 + 8) * A_STRIDE + kA0]);
                a[mi][2] = __float_as_uint(Ab[(mi * 16 + 0) * A_STRIDE + kA1]);
                a[mi][3] = __float_as_uint(Ab[(mi * 16 + 8) * A_STRIDE + kA1]);
            }
            #pragma unroll
            for (int nj = 0; nj < 4; nj++) {
                b[nj][0] = __float_as_uint(Wb[kA0 * W_STRIDE + nj * 8]);
                b[nj][1] = __float_as_uint(Wb[kA1 * W_STRIDE + nj * 8]);
            }
            #pragma unroll
            for (int mi = 0; mi < 4; mi++)
                #pragma unroll
                for (int nj = 0; nj < 4; nj++) {
                    asm volatile(
                        "mma.sync.aligned.m16n8k8.row.col.f32.tf32.tf32.f32 "
                        "{%0,%1,%2,%3}, {%4,%5,%6,%7}, {%8,%9}, {%0,%1,%2,%3};"
                        : "+f"(acc[mi][nj][0]), "+f"(acc[mi][nj][1]),
                          "+f"(acc[mi][nj][2]), "+f"(acc[mi][nj][3])
                        : "r"(a[mi][0]), "r"(a[mi][1]), "r"(a[mi][2]), "r"(a[mi][3]),
                          "r"(b[nj][0]), "r"(b[nj][1]));
                }
        }
        __syncthreads();
    }

    if (round_out) {
        #pragma unroll
        for (int mi = 0; mi < 4; mi++) {
            int row = bm + warp_m * 64 + mi * 16 + qid;
            #pragma unroll
            for (int nj = 0; nj < 4; nj++) {
                int col = bn + warp_n * 32 + nj * 8 + tg * 2;
                float b0 = bias[col], b1 = bias[col + 1];
                float2 v0 = make_float2(to_tf32(acc[mi][nj][0] + b0), to_tf32(acc[mi][nj][1] + b1));
                float2 v1 = make_float2(to_tf32(acc[mi][nj][2] + b0), to_tf32(acc[mi][nj][3] + b1));
                *reinterpret_cast<float2*>(&C[(size_t)row * DMODEL + col]) = v0;
                *reinterpret_cast<float2*>(&C[(size_t)(row + 8) * DMODEL + col]) = v1;
            }
        }
    } else {
        #pragma unroll
        for (int mi = 0; mi < 4; mi++) {
            int row = bm + warp_m * 64 + mi * 16 + qid;
            #pragma unroll
            for (int nj = 0; nj < 4; nj++) {
                int col = bn + warp_n * 32 + nj * 8 + tg * 2;
                float b0 = bias[col], b1 = bias[col + 1];
                float2 v0 = make_float2(acc[mi][nj][0] + b0, acc[mi][nj][1] + b1);
                float2 v1 = make_float2(acc[mi][nj][2] + b0, acc[mi][nj][3] + b1);
                *reinterpret_cast<float2*>(&C[(size_t)row * DMODEL + col]) = v0;
                *reinterpret_cast<float2*>(&C[(size_t)(row + 8) * DMODEL + col]) = v1;
            }
        }
    }
}

// ------------- tf32 tensor-core causal flash attention -------------
// CTA: 64 q-rows, 4 warps (128 thr), each warp owns 16 rows x full 64-key width.
// 2-3 CTAs/SM co-resident -> softmax of one CTA overlaps mma of another.
// Q/K/V tf32-pre-rounded by QKV GEMM epilogue -> no cvt on loads.
// Heavy tiles first: qt = gridDim.x-1-blockIdx.x (causal load-balance).
__global__ __launch_bounds__(128, 3)
void attn_tc_kernel(const float* __restrict__ Q, const float* __restrict__ K,
                    const float* __restrict__ V, float* __restrict__ O) {
    __shared__ float Ks[16 * 256];   // 16KB
    __shared__ float Vs[64 * 72];    // 18KB
    const int qt = gridDim.x - 1 - blockIdx.x;   // heavy tiles scheduled first
    const int h = blockIdx.y, b = blockIdx.z;
    const int tid = threadIdx.x;
    const int lane = tid & 31;
    const int w = tid >> 5;          // 0..3
    const int q4 = lane >> 2;        // group id 0..7
    const int r4 = lane & 3;         // thread-in-group 0..3
    const size_t base = (size_t)b * SEQ * DMODEL + (size_t)h * HD;

    const int row0 = qt * 64 + w * 16 + q4;   // this thread's first q row

    // ---- Q fragments (pre-rounded tf32; pow2 scale exact) ----
    unsigned qf[8][4];
    {
        const float* Qp = Q + base + (size_t)row0 * DMODEL;
        #pragma unroll
        for (int ks = 0; ks < 8; ks++) {
            qf[ks][0] = __float_as_uint(Qp[ks * 8 + r4] * 0.125f);
            qf[ks][1] = __float_as_uint(Qp[8 * DMODEL + ks * 8 + r4] * 0.125f);
            qf[ks][2] = __float_as_uint(Qp[ks * 8 + r4 + 4] * 0.125f);
            qf[ks][3] = __float_as_uint(Qp[8 * DMODEL + ks * 8 + r4 + 4] * 0.125f);
        }
    }

    float m0 = -1e30f, m1 = -1e30f, l0 = 0.f, l1 = 0.f;
    float oacc[8][4];
    #pragma unroll
    for (int of = 0; of < 8; of++)
        #pragma unroll
        for (int r = 0; r < 4; r++) oacc[of][r] = 0.f;

    const int jmax = qt;             // 64-key tiles; diagonal at j == qt
    for (int j = 0; j <= jmax; j++) {
        __syncthreads();
        // ---- load K (transposed, swizzled) and V tiles (no cvt; pre-rounded) ----
        #pragma unroll
        for (int l = 0; l < 8; l++) {
            int f = tid + l * 128;          // 0..1023
            int n = f >> 4;                 // key 0..63
            int dblk = f & 15;              // d/4 block
            float4 kv = *reinterpret_cast<const float4*>(
                K + base + (size_t)(j * 64 + n) * DMODEL + dblk * 4);
            *reinterpret_cast<float4*>(&Ks[dblk * 256 + ((n ^ (dblk & 7)) << 2)]) = kv;

            float4 vv = *reinterpret_cast<const float4*>(
                V + base + (size_t)(j * 64 + n) * DMODEL + dblk * 4);
            *reinterpret_cast<float4*>(&Vs[n * 72 + dblk * 4]) = vv;
        }
        __syncthreads();

        // ---- S = (Q/8) K^T : 8 n-frags ----
        float sacc[8][4];
        #pragma unroll
        for (int nf = 0; nf < 8; nf++)
            #pragma unroll
            for (int r = 0; r < 4; r++) sacc[nf][r] = 0.f;

        #pragma unroll
        for (int ks = 0; ks < 8; ks++) {
            const int p0 = (2 * ks) * 256 + ((q4 ^ ((2 * ks) & 7)) << 2) + r4;
            const int p1 = (2 * ks + 1) * 256 + ((q4 ^ ((2 * ks + 1) & 7)) << 2) + r4;
            #pragma unroll
            for (int nf = 0; nf < 8; nf++) {
                unsigned b0 = __float_as_uint(Ks[p0 + nf * 32]);
                unsigned b1 = __float_as_uint(Ks[p1 + nf * 32]);
                asm volatile(
                    "mma.sync.aligned.m16n8k8.row.col.f32.tf32.tf32.f32 "
                    "{%0,%1,%2,%3}, {%4,%5,%6,%7}, {%8,%9}, {%0,%1,%2,%3};"
                    : "+f"(sacc[nf][0]), "+f"(sacc[nf][1]),
                      "+f"(sacc[nf][2]), "+f"(sacc[nf][3])
                    : "r"(qf[ks][0]), "r"(qf[ks][1]), "r"(qf[ks][2]), "r"(qf[ks][3]),
                      "r"(b0), "r"(b1));
            }
        }

        // ---- causal mask (diagonal tile only) ----
        if (j == qt) {
            int gcol0 = j * 64 + r4 * 2;
            #pragma unroll
            for (int nf = 0; nf < 8; nf++) {
                int c = gcol0 + nf * 8;
                if (c     > row0)     sacc[nf][0] = -1e30f;
                if (c + 1 > row0)     sacc[nf][1] = -1e30f;
                if (c     > row0 + 8) sacc[nf][2] = -1e30f;
                if (c + 1 > row0 + 8) sacc[nf][3] = -1e30f;
            }
        }

        // ---- online softmax ----
        float rmax0 = -1e30f, rmax1 = -1e30f;
        #pragma unroll
        for (int nf = 0; nf < 8; nf++) {
            rmax0 = fmaxf(rmax0, fmaxf(sacc[nf][0], sacc[nf][1]));
            rmax1 = fmaxf(rmax1, fmaxf(sacc[nf][2], sacc[nf][3]));
        }
        rmax0 = fmaxf(rmax0, __shfl_xor_sync(0xffffffffu, rmax0, 1));
        rmax0 = fmaxf(rmax0, __shfl_xor_sync(0xffffffffu, rmax0, 2));
        rmax1 = fmaxf(rmax1, __shfl_xor_sync(0xffffffffu, rmax1, 1));
        rmax1 = fmaxf(rmax1, __shfl_xor_sync(0xffffffffu, rmax1, 2));
        float mn0 = fmaxf(m0, rmax0), mn1 = fmaxf(m1, rmax1);
        float al0 = __expf(m0 - mn0), al1 = __expf(m1 - mn1);
        m0 = mn0; m1 = mn1;
        float rs0 = 0.f, rs1 = 0.f;
        #pragma unroll
        for (int nf = 0; nf < 8; nf++) {
            sacc[nf][0] = __expf(sacc[nf][0] - mn0);
            sacc[nf][1] = __expf(sacc[nf][1] - mn0);
            sacc[nf][2] = __expf(sacc[nf][2] - mn1);
            sacc[nf][3] = __expf(sacc[nf][3] - mn1);
            rs0 += sacc[nf][0] + sacc[nf][1];
            rs1 += sacc[nf][2] + sacc[nf][3];
        }
        rs0 += __shfl_xor_sync(0xffffffffu, rs0, 1);
        rs0 += __shfl_xor_sync(0xffffffffu, rs0, 2);
        rs1 += __shfl_xor_sync(0xffffffffu, rs1, 1);
        rs1 += __shfl_xor_sync(0xffffffffu, rs1, 2);
        l0 = l0 * al0 + rs0;
        l1 = l1 * al1 + rs1;
        #pragma unroll
        for (int of = 0; of < 8; of++) {
            oacc[of][0] *= al0; oacc[of][1] *= al0;
            oacc[of][2] *= al1; oacc[of][3] *= al1;
        }

        // ---- O += P @ V (P A-frags built via shfl from sacc) ----
        const int srcA = (lane & 28) | (r4 >> 1);
        const int srcB = srcA | 2;
        const bool odd = (r4 & 1);
        #pragma unroll
        for (int ks = 0; ks < 8; ks++) {
            float v0 = __shfl_sync(0xffffffffu, sacc[ks][0], srcA);
            float v1 = __shfl_sync(0xffffffffu, sacc[ks][1], srcA);
            float v2 = __shfl_sync(0xffffffffu, sacc[ks][2], srcA);
            float v3 = __shfl_sync(0xffffffffu, sacc[ks][3], srcA);
            float u0 = __shfl_sync(0xffffffffu, sacc[ks][0], srcB);
            float u1 = __shfl_sync(0xffffffffu, sacc[ks][1], srcB);
            float u2 = __shfl_sync(0xffffffffu, sacc[ks][2], srcB);
            float u3 = __shfl_sync(0xffffffffu, sacc[ks][3], srcB);
            unsigned a0 = __float_as_uint(to_tf32(odd ? v1 : v0));
            unsigned a1 = __float_as_uint(to_tf32(odd ? v3 : v2));
            unsigned a2 = __float_as_uint(to_tf32(odd ? u1 : u0));
            unsigned a3 = __float_as_uint(to_tf32(odd ? u3 : u2));
            const int vb0 = (ks * 8 + r4) * 72 + q4;
            const int vb1 = (ks * 8 + r4 + 4) * 72 + q4;
            #pragma unroll
            for (int of = 0; of < 8; of++) {
                unsigned b0 = __float_as_uint(Vs[vb0 + of * 8]);
                unsigned b1 = __float_as_uint(Vs[vb1 + of * 8]);
                asm volatile(
                    "mma.sync.aligned.m16n8k8.row.col.f32.tf32.tf32.f32 "
                    "{%0,%1,%2,%3}, {%4,%5,%6,%7}, {%8,%9}, {%0,%1,%2,%3};"
                    : "+f"(oacc[of][0]), "+f"(oacc[of][1]),
                      "+f"(oacc[of][2]), "+f"(oacc[of][3])
                    : "r"(a0), "r"(a1), "r"(a2), "r"(a3),
                      "r"(b0), "r"(b1));
            }
        }
    }

    // ---- epilogue (tf32-rounded for the Wo GEMM) ----
    float inv0 = 1.0f / l0, inv1 = 1.0f / l1;
    #pragma unroll
    for (int of = 0; of < 8; of++) {
        int col = of * 8 + r4 * 2;
        float2 w0 = make_float2(to_tf32(oacc[of][0] * inv0), to_tf32(oacc[of][1] * inv0));
        float2 w1 = make_float2(to_tf32(oacc[of][2] * inv1), to_tf32(oacc[of][3] * inv1));
        *reinterpret_cast<float2*>(&O[base + (size_t)row0 * DMODEL + col]) = w0;
        *reinterpret_cast<float2*>(&O[base + (size_t)(row0 + 8) * DMODEL + col]) = w1;
    }
}

extern "C" void kernel_launch(void* const* d_in, const int* in_sizes, int n_in,
                              void* d_out, int out_size) {
    (void)in_sizes; (void)n_in; (void)out_size;
    const float* x     = (const float*)d_in[0];
    const float* Wq    = (const float*)d_in[1];
    const float* bq    = (const float*)d_in[2];
    const float* Wk    = (const float*)d_in[3];
    const float* bk    = (const float*)d_in[4];
    const float* Wv    = (const float*)d_in[5];
    const float* bv    = (const float*)d_in[6];
    const float* Wo    = (const float*)d_in[7];
    const float* bo    = (const float*)d_in[8];
    const float* gamma = (const float*)d_in[9];
    const float* beta  = (const float*)d_in[10];
    float* out = (float*)d_out;

    float *h, *q, *k, *v, *attn, *wq, *wk, *wv, *wo;
    cudaGetSymbolAddress((void**)&h,    g_h);
    cudaGetSymbolAddress((void**)&q,    g_q);
    cudaGetSymbolAddress((void**)&k,    g_k);
    cudaGetSymbolAddress((void**)&v,    g_v);
    cudaGetSymbolAddress((void**)&attn, g_attn);
    cudaGetSymbolAddress((void**)&wq,   g_wq);
    cudaGetSymbolAddress((void**)&wk,   g_wk);
    cudaGetSymbolAddress((void**)&wv,   g_wv);
    cudaGetSymbolAddress((void**)&wo,   g_wo);

    // pre-round weights to tf32 (rna) in one launch
    dim3 rgrid((DMODEL * DMODEL / 4) / 256, 1, 4);
    round_tf32_kernel<<<rgrid, 256>>>(Wq, wq, Wk, wk, Wv, wv, Wo, wo);

    ln_kernel<<<MROWS / 8, 256>>>(x, gamma, beta, h);

    // fused QKV projection: one launch, z selects (W, bias, C); outputs tf32-rounded
    dim3 gqkv(DMODEL / 128, MROWS / 128, 3);   // (8, 64, 3)
    gemm_bias_kernel<<<gqkv, 256>>>(h, wq, bq, q, wk, bk, k, wv, bv, v, 1);

    attn_tc_kernel<<<dim3(SEQ / 64, NHEAD, BATCH), 128>>>(q, k, v, attn);

    dim3 go(DMODEL / 128, MROWS / 128, 1);
    gemm_bias_kernel<<<go, 256>>>(attn, wo, bo, out, wo, bo, out, wo, bo, out, 0);
}

// round 16
// speedup vs baseline: 1.2158x; 1.0276x over previous
#include <cuda_runtime.h>
#include <cuda_fp16.h>
#include <math.h>

#define DMODEL 1024
#define NHEAD  16
#define HD     64
#define BATCH  4
#define SEQ    2048
#define MROWS  (BATCH*SEQ)   // 8192

#define SSTR 72   // halves per smem row (144B: frag banks 4*row+r4, conflict-free)

// Scratch (allocation-free rule: __device__ globals)
__device__ __half g_h[MROWS*DMODEL];
__device__ __half g_q[MROWS*DMODEL];
__device__ __half g_k[MROWS*DMODEL];
__device__ __half g_v[MROWS*DMODEL];
__device__ __half g_vT[BATCH*NHEAD*HD*SEQ];   // [b][h][d][s]
__device__ __half g_attn[MROWS*DMODEL];
// fp16 weights, TRANSPOSED to [n][k]
__device__ __half g_wq[DMODEL*DMODEL];
__device__ __half g_wk[DMODEL*DMODEL];
__device__ __half g_wv[DMODEL*DMODEL];
__device__ __half g_wo[DMODEL*DMODEL];

__device__ __forceinline__ unsigned ldh2(const __half* p) {
    return *reinterpret_cast<const unsigned*>(p);
}
__device__ __forceinline__ unsigned packh2(float a, float b) {
    __half2 h = __floats2half2_rn(a, b);
    return *reinterpret_cast<unsigned*>(&h);
}
__device__ __forceinline__ unsigned smem_u32(const void* p) {
    return (unsigned)__cvta_generic_to_shared(p);
}
__device__ __forceinline__ void cp_async8(unsigned saddr, const void* gptr) {
    asm volatile("cp.async.ca.shared.global [%0], [%1], 8;\n" :: "r"(saddr), "l"(gptr));
}

// ---------------- weight round->fp16 + transpose: WT[n][k] = (half)W[k][n] ----------------
__global__ void wt_kernel(const float* __restrict__ s0, __half* __restrict__ d0,
                          const float* __restrict__ s1, __half* __restrict__ d1,
                          const float* __restrict__ s2, __half* __restrict__ d2,
                          const float* __restrict__ s3, __half* __restrict__ d3) {
    const float* src; __half* dst;
    if (blockIdx.z == 0)      { src = s0; dst = d0; }
    else if (blockIdx.z == 1) { src = s1; dst = d1; }
    else if (blockIdx.z == 2) { src = s2; dst = d2; }
    else                      { src = s3; dst = d3; }
    __shared__ float tile[32][33];
    int bn = blockIdx.x * 32;   // n
    int bk = blockIdx.y * 32;   // k
    int tx = threadIdx.x, ty = threadIdx.y;   // 32 x 8
    #pragma unroll
    for (int i = 0; i < 32; i += 8)
        tile[ty + i][tx] = src[(size_t)(bk + ty + i) * DMODEL + bn + tx];   // tile[k][n]
    __syncthreads();
    #pragma unroll
    for (int i = 0; i < 32; i += 8)
        dst[(size_t)(bn + ty + i) * DMODEL + bk + tx] = __float2half_rn(tile[tx][ty + i]);
}

// ---------------- V transpose: vT[b][h][d][s] = v[b*S+s][h*64+d] ----------------
__global__ void vtrans_kernel(const __half* __restrict__ v, __half* __restrict__ vT) {
    __shared__ __half tile[64][SSTR];
    const int s0 = blockIdx.x * 64, h = blockIdx.y, b = blockIdx.z;
    const int tid = threadIdx.x;   // 256
    const __half* src = v + ((size_t)b * SEQ + s0) * DMODEL + h * HD;
    #pragma unroll
    for (int l = 0; l < 2; l++) {
        int f = tid + l * 256;      // 0..511
        int sr = f >> 3, dc = f & 7;
        float4 x = *reinterpret_cast<const float4*>(src + (size_t)sr * DMODEL + dc * 8);
        const __half* hp = reinterpret_cast<const __half*>(&x);
        #pragma unroll
        for (int i = 0; i < 8; i++) tile[dc * 8 + i][sr] = hp[i];
    }
    __syncthreads();
    __half* dst = vT + ((size_t)(b * NHEAD + h) * HD) * SEQ + s0;
    #pragma unroll
    for (int l = 0; l < 2; l++) {
        int f = tid + l * 256;
        int dr = f >> 3, sc = f & 7;
        *reinterpret_cast<float4*>(dst + (size_t)dr * SEQ + sc * 8) =
            *reinterpret_cast<const float4*>(&tile[dr][sc * 8]);
    }
}

// ---------------- LayerNorm: one WARP per row, fp16 output ----------------
__global__ void ln_kernel(const float* __restrict__ x,
                          const float* __restrict__ gamma,
                          const float* __restrict__ beta,
                          __half* __restrict__ out) {
    const int lane = threadIdx.x & 31;
    const int row = blockIdx.x * 8 + (threadIdx.x >> 5);
    const float* xr = x + (size_t)row * DMODEL;
    __half2* orow = reinterpret_cast<__half2*>(out + (size_t)row * DMODEL);

    float4 xv[8];
    float s = 0.f, s2 = 0.f;
    #pragma unroll
    for (int i = 0; i < 8; i++) {
        xv[i] = reinterpret_cast<const float4*>(xr)[lane + i * 32];
        s  += xv[i].x + xv[i].y + xv[i].z + xv[i].w;
        s2 += xv[i].x*xv[i].x + xv[i].y*xv[i].y + xv[i].z*xv[i].z + xv[i].w*xv[i].w;
    }
    #pragma unroll
    for (int o = 16; o; o >>= 1) {
        s  += __shfl_xor_sync(0xffffffffu, s,  o);
        s2 += __shfl_xor_sync(0xffffffffu, s2, o);
    }
    float mean = s * (1.0f / DMODEL);
    float var  = s2 * (1.0f / DMODEL) - mean * mean;
    float rstd = rsqrtf(var + 1e-5f);
    #pragma unroll
    for (int i = 0; i < 8; i++) {
        float4 gv = reinterpret_cast<const float4*>(gamma)[lane + i * 32];
        float4 bv = reinterpret_cast<const float4*>(beta)[lane + i * 32];
        int p = (lane + i * 32) * 2;
        orow[p]     = __floats2half2_rn((xv[i].x - mean) * rstd * gv.x + bv.x,
                                        (xv[i].y - mean) * rstd * gv.y + bv.y);
        orow[p + 1] = __floats2half2_rn((xv[i].z - mean) * rstd * gv.z + bv.z,
                                        (xv[i].w - mean) * rstd * gv.w + bv.w);
    }
}

// ------------- fp16 GEMM 128x128x32, cp.async double-buffered, mma.m16n8k16 -------------
// C = A@W + bias; A [m][k] fp16, W pre-transposed [n][k] fp16. blockIdx.z selects triple.
// round_out: 1 -> write fp16 (q/k/v/attn path), 0 -> write fp32 (final out).
__global__ __launch_bounds__(256, 2)
void gemm_bias_kernel(const __half* __restrict__ A,
                      const __half* __restrict__ W0, const float* __restrict__ bias0, void* __restrict__ C0,
                      const __half* __restrict__ W1, const float* __restrict__ bias1, void* __restrict__ C1,
                      const __half* __restrict__ W2, const float* __restrict__ bias2, void* __restrict__ C2,
                      int round_out) {
    const __half* W; const float* bias; void* C;
    if (blockIdx.z == 0)      { W = W0; bias = bias0; C = C0; }
    else if (blockIdx.z == 1) { W = W1; bias = bias1; C = C1; }
    else                      { W = W2; bias = bias2; C = C2; }

    __shared__ __half As[2][128 * SSTR];   // [m][k] pad, 18.4KB each
    __shared__ __half Ws[2][128 * SSTR];   // [n][k] pad

    const int tid = threadIdx.x;
    const int bm = blockIdx.y * 128;
    const int bn = blockIdx.x * 128;
    const int lane = tid & 31;
    const int wid  = tid >> 5;
    const int warp_m = wid & 1;
    const int warp_n = wid >> 1;
    const int q4 = lane >> 2;
    const int r4 = lane & 3;

    float acc[4][4][4];
    #pragma unroll
    for (int mi = 0; mi < 4; mi++)
        #pragma unroll
        for (int nj = 0; nj < 4; nj++)
            #pragma unroll
            for (int r = 0; r < 4; r++) acc[mi][nj][r] = 0.f;

    auto issue_tile = [&](int s, int k0) {
        #pragma unroll
        for (int l = 0; l < 4; l++) {
            int f  = tid + l * 256;          // 0..1023
            int m  = f >> 3;                 // 0..127
            int kc = f & 7;                  // 8B chunk (4 halves)
            cp_async8(smem_u32(&As[s][m * SSTR + kc * 4]),
                      A + (size_t)(bm + m) * DMODEL + k0 + kc * 4);
        }
        #pragma unroll
        for (int l = 0; l < 4; l++) {
            int f  = tid + l * 256;
            int n  = f >> 3;
            int kc = f & 7;
            cp_async8(smem_u32(&Ws[s][n * SSTR + kc * 4]),
                      W + (size_t)(bn + n) * DMODEL + k0 + kc * 4);
        }
        asm volatile("cp.async.commit_group;\n");
    };

    issue_tile(0, 0);

    const int NITER = DMODEL / 32;
    for (int it = 0; it < NITER; it++) {
        const int s = it & 1;
        if (it + 1 < NITER) {
            issue_tile(s ^ 1, (it + 1) * 32);
            asm volatile("cp.async.wait_group 1;\n");
        } else {
            asm volatile("cp.async.wait_group 0;\n");
        }
        __syncthreads();

        const __half* Ab = &As[s][(warp_m * 64 + q4) * SSTR];
        const __half* Wb = &Ws[s][(warp_n * 32 + q4) * SSTR];
        #pragma unroll
        for (int c16 = 0; c16 < 2; c16++) {
            const int ka = c16 * 16 + r4 * 2;
            unsigned a[4][4], b[4][2];
            #pragma unroll
            for (int mi = 0; mi < 4; mi++) {
                a[mi][0] = ldh2(Ab + (mi * 16 + 0) * SSTR + ka);
                a[mi][1] = ldh2(Ab + (mi * 16 + 8) * SSTR + ka);
                a[mi][2] = ldh2(Ab + (mi * 16 + 0) * SSTR + ka + 8);
                a[mi][3] = ldh2(Ab + (mi * 16 + 8) * SSTR + ka + 8);
            }
            #pragma unroll
            for (int nj = 0; nj < 4; nj++) {
                b[nj][0] = ldh2(Wb + (nj * 8) * SSTR + ka);
                b[nj][1] = ldh2(Wb + (nj * 8) * SSTR + ka + 8);
            }
            #pragma unroll
            for (int mi = 0; mi < 4; mi++)
                #pragma unroll
                for (int nj = 0; nj < 4; nj++) {
                    asm volatile(
                        "mma.sync.aligned.m16n8k16.row.col.f32.f16.f16.f32 "
                        "{%0,%1,%2,%3}, {%4,%5,%6,%7}, {%8,%9}, {%0,%1,%2,%3};"
                        : "+f"(acc[mi][nj][0]), "+f"(acc[mi][nj][1]),
                          "+f"(acc[mi][nj][2]), "+f"(acc[mi][nj][3])
                        : "r"(a[mi][0]), "r"(a[mi][1]), "r"(a[mi][2]), "r"(a[mi][3]),
                          "r"(b[nj][0]), "r"(b[nj][1]));
                }
        }
        __syncthreads();
    }

    const int tg = r4;
    if (round_out) {
        __half* Ch = (__half*)C;
        #pragma unroll
        for (int mi = 0; mi < 4; mi++) {
            int row = bm + warp_m * 64 + mi * 16 + q4;
            #pragma unroll
            for (int nj = 0; nj < 4; nj++) {
                int col = bn + warp_n * 32 + nj * 8 + tg * 2;
                float b0 = bias[col], b1 = bias[col + 1];
                *reinterpret_cast<__half2*>(&Ch[(size_t)row * DMODEL + col]) =
                    __floats2half2_rn(acc[mi][nj][0] + b0, acc[mi][nj][1] + b1);
                *reinterpret_cast<__half2*>(&Ch[(size_t)(row + 8) * DMODEL + col]) =
                    __floats2half2_rn(acc[mi][nj][2] + b0, acc[mi][nj][3] + b1);
            }
        }
    } else {
        float* Cf = (float*)C;
        #pragma unroll
        for (int mi = 0; mi < 4; mi++) {
            int row = bm + warp_m * 64 + mi * 16 + q4;
            #pragma unroll
            for (int nj = 0; nj < 4; nj++) {
                int col = bn + warp_n * 32 + nj * 8 + tg * 2;
                float b0 = bias[col], b1 = bias[col + 1];
                float2 v0 = make_float2(acc[mi][nj][0] + b0, acc[mi][nj][1] + b1);
                float2 v1 = make_float2(acc[mi][nj][2] + b0, acc[mi][nj][3] + b1);
                *reinterpret_cast<float2*>(&Cf[(size_t)row * DMODEL + col]) = v0;
                *reinterpret_cast<float2*>(&Cf[(size_t)(row + 8) * DMODEL + col]) = v1;
            }
        }
    }
}

// ------------- fp16 tensor-core causal flash attention, mma.m16n8k16 -------------
// CTA: 64 q-rows, 4 warps. QK C-frag == PV A-frag layout -> no shfl transpose.
// Ks [key][d] fp16, VsT [d][key] fp16 (from pre-transposed g_vT), stride 72 halves.
__global__ __launch_bounds__(128, 3)
void attn_tc_kernel(const __half* __restrict__ Q, const __half* __restrict__ K,
                    const __half* __restrict__ Vt, __half* __restrict__ O) {
    __shared__ __half Ks[64 * SSTR];   // 9.2KB
    __shared__ __half Vs[64 * SSTR];   // 9.2KB
    const int qt = gridDim.x - 1 - blockIdx.x;   // heavy tiles first
    const int h = blockIdx.y, b = blockIdx.z;
    const int tid = threadIdx.x;
    const int lane = tid & 31;
    const int w = tid >> 5;          // 0..3
    const int q4 = lane >> 2;
    const int r4 = lane & 3;
    const size_t base  = (size_t)b * SEQ * DMODEL + (size_t)h * HD;
    const size_t vbase = ((size_t)(b * NHEAD + h) * HD) * SEQ;

    const int row0 = qt * 64 + w * 16 + q4;

    // ---- Q fragments: 4 k16-chunks x 4 half2 regs, scale 1/8 exact ----
    unsigned qf[4][4];
    {
        const __half* Qp = Q + base + (size_t)row0 * DMODEL;
        const __half2 sc = __floats2half2_rn(0.125f, 0.125f);
        #pragma unroll
        for (int c = 0; c < 4; c++) {
            int d0 = c * 16 + r4 * 2;
            #pragma unroll
            for (int r = 0; r < 4; r++) {
                int off = d0 + ((r >> 1) ? 8 : 0) + ((r & 1) ? 8 * DMODEL : 0);
                unsigned u = ldh2(Qp + off);
                __half2 hv = *reinterpret_cast<__half2*>(&u);
                hv = __hmul2(hv, sc);
                qf[c][r] = *reinterpret_cast<unsigned*>(&hv);
            }
        }
        // qf[c][0]=row0,d0 ; [1]=row0+8,d0 ; [2]=row0,d0+8 ; [3]=row0+8,d0+8
    }

    float m0 = -1e30f, m1 = -1e30f, l0 = 0.f, l1 = 0.f;
    float oacc[8][4];
    #pragma unroll
    for (int of = 0; of < 8; of++)
        #pragma unroll
        for (int r = 0; r < 4; r++) oacc[of][r] = 0.f;

    const int jmax = qt;
    for (int j = 0; j <= jmax; j++) {
        __syncthreads();
        // ---- load K [key][d] and Vt [d][key] tiles (fp16, coalesced float4) ----
        const __half* Kp = K + base + (size_t)(j * 64) * DMODEL;
        const __half* Vp = Vt + vbase + j * 64;
        #pragma unroll
        for (int l = 0; l < 4; l++) {
            int f = tid + l * 128;          // 0..511
            int n = f >> 3, dc = f & 7;
            *reinterpret_cast<float4*>(&Ks[n * SSTR + dc * 8]) =
                *reinterpret_cast<const float4*>(Kp + (size_t)n * DMODEL + dc * 8);
            *reinterpret_cast<float4*>(&Vs[n * SSTR + dc * 8]) =
                *reinterpret_cast<const float4*>(Vp + (size_t)n * SEQ + dc * 8);
        }
        __syncthreads();

        // ---- S = (Q/8) K^T : 4 k16-chunks x 8 n-frags ----
        float sacc[8][4];
        #pragma unroll
        for (int nf = 0; nf < 8; nf++)
            #pragma unroll
            for (int r = 0; r < 4; r++) sacc[nf][r] = 0.f;

        #pragma unroll
        for (int c = 0; c < 4; c++) {
            const int ka = c * 16 + r4 * 2;
            #pragma unroll
            for (int nf = 0; nf < 8; nf++) {
                const __half* kp = &Ks[(nf * 8 + q4) * SSTR + ka];
                unsigned b0 = ldh2(kp);
                unsigned b1 = ldh2(kp + 8);
                asm volatile(
                    "mma.sync.aligned.m16n8k16.row.col.f32.f16.f16.f32 "
                    "{%0,%1,%2,%3}, {%4,%5,%6,%7}, {%8,%9}, {%0,%1,%2,%3};"
                    : "+f"(sacc[nf][0]), "+f"(sacc[nf][1]),
                      "+f"(sacc[nf][2]), "+f"(sacc[nf][3])
                    : "r"(qf[c][0]), "r"(qf[c][1]), "r"(qf[c][2]), "r"(qf[c][3]),
                      "r"(b0), "r"(b1));
            }
        }

        // ---- causal mask (diagonal tile only) ----
        if (j == qt) {
            int gcol0 = j * 64 + r4 * 2;
            #pragma unroll
            for (int nf = 0; nf < 8; nf++) {
                int cix = gcol0 + nf * 8;
                if (cix     > row0)     sacc[nf][0] = -1e30f;
                if (cix + 1 > row0)     sacc[nf][1] = -1e30f;
                if (cix     > row0 + 8) sacc[nf][2] = -1e30f;
                if (cix + 1 > row0 + 8) sacc[nf][3] = -1e30f;
            }
        }

        // ---- online softmax (rows row0 / row0+8) ----
        float rmax0 = -1e30f, rmax1 = -1e30f;
        #pragma unroll
        for (int nf = 0; nf < 8; nf++) {
            rmax0 = fmaxf(rmax0, fmaxf(sacc[nf][0], sacc[nf][1]));
            rmax1 = fmaxf(rmax1, fmaxf(sacc[nf][2], sacc[nf][3]));
        }
        rmax0 = fmaxf(rmax0, __shfl_xor_sync(0xffffffffu, rmax0, 1));
        rmax0 = fmaxf(rmax0, __shfl_xor_sync(0xffffffffu, rmax0, 2));
        rmax1 = fmaxf(rmax1, __shfl_xor_sync(0xffffffffu, rmax1, 1));
        rmax1 = fmaxf(rmax1, __shfl_xor_sync(0xffffffffu, rmax1, 2));
        float mn0 = fmaxf(m0, rmax0), mn1 = fmaxf(m1, rmax1);
        float al0 = __expf(m0 - mn0), al1 = __expf(m1 - mn1);
        m0 = mn0; m1 = mn1;
        float rs0 = 0.f, rs1 = 0.f;
        #pragma unroll
        for (int nf = 0; nf < 8; nf++) {
            sacc[nf][0] = __expf(sacc[nf][0] - mn0);
            sacc[nf][1] = __expf(sacc[nf][1] - mn0);
            sacc[nf][2] = __expf(sacc[nf][2] - mn1);
            sacc[nf][3] = __expf(sacc[nf][3] - mn1);
            rs0 += sacc[nf][0] + sacc[nf][1];
            rs1 += sacc[nf][2] + sacc[nf][3];
        }
        rs0 += __shfl_xor_sync(0xffffffffu, rs0, 1);
        rs0 += __shfl_xor_sync(0xffffffffu, rs0, 2);
        rs1 += __shfl_xor_sync(0xffffffffu, rs1, 1);
        rs1 += __shfl_xor_sync(0xffffffffu, rs1, 2);
        l0 = l0 * al0 + rs0;
        l1 = l1 * al1 + rs1;
        #pragma unroll
        for (int of = 0; of < 8; of++) {
            oacc[of][0] *= al0; oacc[of][1] *= al0;
            oacc[of][2] *= al1; oacc[of][3] *= al1;
        }

        // ---- O += P @ V : QK C-frag == PV A-frag, just pack to fp16 ----
        #pragma unroll
        for (int c = 0; c < 4; c++) {
            unsigned a0 = packh2(sacc[2 * c][0],     sacc[2 * c][1]);
            unsigned a1 = packh2(sacc[2 * c][2],     sacc[2 * c][3]);
            unsigned a2 = packh2(sacc[2 * c + 1][0], sacc[2 * c + 1][1]);
            unsigned a3 = packh2(sacc[2 * c + 1][2], sacc[2 * c + 1][3]);
            const int kk = c * 16 + r4 * 2;
            #pragma unroll
            for (int of = 0; of < 8; of++) {
                const __half* vp = &Vs[(of * 8 + q4) * SSTR + kk];
                unsigned b0 = ldh2(vp);
                unsigned b1 = ldh2(vp + 8);
                asm volatile(
                    "mma.sync.aligned.m16n8k16.row.col.f32.f16.f16.f32 "
                    "{%0,%1,%2,%3}, {%4,%5,%6,%7}, {%8,%9}, {%0,%1,%2,%3};"
                    : "+f"(oacc[of][0]), "+f"(oacc[of][1]),
                      "+f"(oacc[of][2]), "+f"(oacc[of][3])
                    : "r"(a0), "r"(a1), "r"(a2), "r"(a3),
                      "r"(b0), "r"(b1));
            }
        }
    }

    // ---- epilogue: fp16 out for the Wo GEMM ----
    float inv0 = 1.0f / l0, inv1 = 1.0f / l1;
    #pragma unroll
    for (int of = 0; of < 8; of++) {
        int col = of * 8 + r4 * 2;
        *reinterpret_cast<__half2*>(&O[base + (size_t)row0 * DMODEL + col]) =
            __floats2half2_rn(oacc[of][0] * inv0, oacc[of][1] * inv0);
        *reinterpret_cast<__half2*>(&O[base + (size_t)(row0 + 8) * DMODEL + col]) =
            __floats2half2_rn(oacc[of][2] * inv1, oacc[of][3] * inv1);
    }
}

extern "C" void kernel_launch(void* const* d_in, const int* in_sizes, int n_in,
                              void* d_out, int out_size) {
    (void)in_sizes; (void)n_in; (void)out_size;
    const float* x     = (const float*)d_in[0];
    const float* Wq    = (const float*)d_in[1];
    const float* bq    = (const float*)d_in[2];
    const float* Wk    = (const float*)d_in[3];
    const float* bk    = (const float*)d_in[4];
    const float* Wv    = (const float*)d_in[5];
    const float* bv    = (const float*)d_in[6];
    const float* Wo    = (const float*)d_in[7];
    const float* bo    = (const float*)d_in[8];
    const float* gamma = (const float*)d_in[9];
    const float* beta  = (const float*)d_in[10];
    float* out = (float*)d_out;

    __half *h, *q, *k, *v, *vT, *attn, *wq, *wk, *wv, *wo;
    cudaGetSymbolAddress((void**)&h,    g_h);
    cudaGetSymbolAddress((void**)&q,    g_q);
    cudaGetSymbolAddress((void**)&k,    g_k);
    cudaGetSymbolAddress((void**)&v,    g_v);
    cudaGetSymbolAddress((void**)&vT,   g_vT);
    cudaGetSymbolAddress((void**)&attn, g_attn);
    cudaGetSymbolAddress((void**)&wq,   g_wq);
    cudaGetSymbolAddress((void**)&wk,   g_wk);
    cudaGetSymbolAddress((void**)&wv,   g_wv);
    cudaGetSymbolAddress((void**)&wo,   g_wo);

    // weights: fp32 -> fp16 + transpose to [n][k]
    wt_kernel<<<dim3(32, 32, 4), dim3(32, 8)>>>(Wq, wq, Wk, wk, Wv, wv, Wo, wo);

    ln_kernel<<<MROWS / 8, 256>>>(x, gamma, beta, h);

    // fused QKV projection (fp16 out)
    dim3 gqkv(DMODEL / 128, MROWS / 128, 3);
    gemm_bias_kernel<<<gqkv, 256>>>(h, wq, bq, q, wk, bk, k, wv, bv, v, 1);

    // V -> [b][h][d][s]
    vtrans_kernel<<<dim3(SEQ / 64, NHEAD, BATCH), 256>>>(v, vT);

    attn_tc_kernel<<<dim3(SEQ / 64, NHEAD, BATCH), 128>>>(q, k, vT, attn);

    dim3 go(DMODEL / 128, MROWS / 128, 1);
    gemm_bias_kernel<<<go, 256>>>(attn, wo, bo, out, wo, bo, out, wo, bo, out, 0);
}

// round 17
// speedup vs baseline: 2.3038x; 1.8949x over previous
#include <cuda_runtime.h>
#include <cuda_fp16.h>
#include <math.h>

#define DMODEL 1024
#define NHEAD  16
#define HD     64
#define BATCH  4
#define SEQ    2048
#define MROWS  (BATCH*SEQ)   // 8192

#define SSTR 72    // halves per K/A/W smem row (144B = 36 words == 4 mod 32)
#define VSTR 136   // halves per V smem row (272B = 68 words == 4 mod 32)

// Scratch (allocation-free rule: __device__ globals)
__device__ __half g_h[MROWS*DMODEL];
__device__ __half g_q[MROWS*DMODEL];
__device__ __half g_k[MROWS*DMODEL];
__device__ __half g_v[MROWS*DMODEL];
__device__ __half g_vT[BATCH*NHEAD*HD*SEQ];   // [b][h][d][s]
__device__ __half g_attn[MROWS*DMODEL];
// fp16 weights, TRANSPOSED to [n][k]
__device__ __half g_wq[DMODEL*DMODEL];
__device__ __half g_wk[DMODEL*DMODEL];
__device__ __half g_wv[DMODEL*DMODEL];
__device__ __half g_wo[DMODEL*DMODEL];

__device__ __forceinline__ unsigned ldh2(const __half* p) {
    return *reinterpret_cast<const unsigned*>(p);
}
__device__ __forceinline__ unsigned packh2(float a, float b) {
    __half2 h = __floats2half2_rn(a, b);
    return *reinterpret_cast<unsigned*>(&h);
}
__device__ __forceinline__ unsigned smem_u32(const void* p) {
    return (unsigned)__cvta_generic_to_shared(p);
}
__device__ __forceinline__ void cp_async8(unsigned saddr, const void* gptr) {
    asm volatile("cp.async.ca.shared.global [%0], [%1], 8;\n" :: "r"(saddr), "l"(gptr));
}
__device__ __forceinline__ void ldsm_x4(unsigned& r0, unsigned& r1, unsigned& r2, unsigned& r3,
                                        const void* p) {
    unsigned addr = smem_u32(p);
    asm volatile("ldmatrix.sync.aligned.m8n8.x4.shared.b16 {%0,%1,%2,%3}, [%4];"
                 : "=r"(r0), "=r"(r1), "=r"(r2), "=r"(r3) : "r"(addr));
}

// ---------------- weight round->fp16 + transpose: WT[n][k] = (half)W[k][n] ----------------
__global__ void wt_kernel(const float* __restrict__ s0, __half* __restrict__ d0,
                          const float* __restrict__ s1, __half* __restrict__ d1,
                          const float* __restrict__ s2, __half* __restrict__ d2,
                          const float* __restrict__ s3, __half* __restrict__ d3) {
    const float* src; __half* dst;
    if (blockIdx.z == 0)      { src = s0; dst = d0; }
    else if (blockIdx.z == 1) { src = s1; dst = d1; }
    else if (blockIdx.z == 2) { src = s2; dst = d2; }
    else                      { src = s3; dst = d3; }
    __shared__ float tile[32][33];
    int bn = blockIdx.x * 32;   // n
    int bk = blockIdx.y * 32;   // k
    int tx = threadIdx.x, ty = threadIdx.y;   // 32 x 8
    #pragma unroll
    for (int i = 0; i < 32; i += 8)
        tile[ty + i][tx] = src[(size_t)(bk + ty + i) * DMODEL + bn + tx];   // tile[k][n]
    __syncthreads();
    #pragma unroll
    for (int i = 0; i < 32; i += 8)
        dst[(size_t)(bn + ty + i) * DMODEL + bk + tx] = __float2half_rn(tile[tx][ty + i]);
}

// ---------------- V transpose: vT[b][h][d][s] = v[b*S+s][h*64+d] ----------------
__global__ void vtrans_kernel(const __half* __restrict__ v, __half* __restrict__ vT) {
    __shared__ __half tile[64][SSTR];
    const int s0 = blockIdx.x * 64, h = blockIdx.y, b = blockIdx.z;
    const int tid = threadIdx.x;   // 256
    const __half* src = v + ((size_t)b * SEQ + s0) * DMODEL + h * HD;
    #pragma unroll
    for (int l = 0; l < 2; l++) {
        int f = tid + l * 256;      // 0..511
        int sr = f >> 3, dc = f & 7;
        float4 x = *reinterpret_cast<const float4*>(src + (size_t)sr * DMODEL + dc * 8);
        const __half* hp = reinterpret_cast<const __half*>(&x);
        #pragma unroll
        for (int i = 0; i < 8; i++) tile[dc * 8 + i][sr] = hp[i];
    }
    __syncthreads();
    __half* dst = vT + ((size_t)(b * NHEAD + h) * HD) * SEQ + s0;
    #pragma unroll
    for (int l = 0; l < 2; l++) {
        int f = tid + l * 256;
        int dr = f >> 3, sc = f & 7;
        *reinterpret_cast<float4*>(dst + (size_t)dr * SEQ + sc * 8) =
            *reinterpret_cast<const float4*>(&tile[dr][sc * 8]);
    }
}

// ---------------- LayerNorm: one WARP per row, fp16 output ----------------
__global__ void ln_kernel(const float* __restrict__ x,
                          const float* __restrict__ gamma,
                          const float* __restrict__ beta,
                          __half* __restrict__ out) {
    const int lane = threadIdx.x & 31;
    const int row = blockIdx.x * 8 + (threadIdx.x >> 5);
    const float* xr = x + (size_t)row * DMODEL;
    __half2* orow = reinterpret_cast<__half2*>(out + (size_t)row * DMODEL);

    float4 xv[8];
    float s = 0.f, s2 = 0.f;
    #pragma unroll
    for (int i = 0; i < 8; i++) {
        xv[i] = reinterpret_cast<const float4*>(xr)[lane + i * 32];
        s  += xv[i].x + xv[i].y + xv[i].z + xv[i].w;
        s2 += xv[i].x*xv[i].x + xv[i].y*xv[i].y + xv[i].z*xv[i].z + xv[i].w*xv[i].w;
    }
    #pragma unroll
    for (int o = 16; o; o >>= 1) {
        s  += __shfl_xor_sync(0xffffffffu, s,  o);
        s2 += __shfl_xor_sync(0xffffffffu, s2, o);
    }
    float mean = s * (1.0f / DMODEL);
    float var  = s2 * (1.0f / DMODEL) - mean * mean;
    float rstd = rsqrtf(var + 1e-5f);
    #pragma unroll
    for (int i = 0; i < 8; i++) {
        float4 gv = reinterpret_cast<const float4*>(gamma)[lane + i * 32];
        float4 bv = reinterpret_cast<const float4*>(beta)[lane + i * 32];
        int p = (lane + i * 32) * 2;
        orow[p]     = __floats2half2_rn((xv[i].x - mean) * rstd * gv.x + bv.x,
                                        (xv[i].y - mean) * rstd * gv.y + bv.y);
        orow[p + 1] = __floats2half2_rn((xv[i].z - mean) * rstd * gv.z + bv.z,
                                        (xv[i].w - mean) * rstd * gv.w + bv.w);
    }
}

// ------------- fp16 GEMM 128x128x64, cp.async 2-stage, ldmatrix frags -------------
// C = A@W + bias; A [m][k] fp16, W pre-transposed [n][k] fp16. blockIdx.z selects triple.
__global__ __launch_bounds__(256, 2)
void gemm_bias_kernel(const __half* __restrict__ A,
                      const __half* __restrict__ W0, const float* __restrict__ bias0, void* __restrict__ C0,
                      const __half* __restrict__ W1, const float* __restrict__ bias1, void* __restrict__ C1,
                      const __half* __restrict__ W2, const float* __restrict__ bias2, void* __restrict__ C2,
                      int round_out) {
    const __half* W; const float* bias; void* C;
    if (blockIdx.z == 0)      { W = W0; bias = bias0; C = C0; }
    else if (blockIdx.z == 1) { W = W1; bias = bias1; C = C1; }
    else                      { W = W2; bias = bias2; C = C2; }

    __shared__ __half As[2][128 * SSTR];   // [m][k0..63] + pad
    __shared__ __half Ws[2][128 * SSTR];   // [n][k0..63] + pad

    const int tid = threadIdx.x;
    const int bm = blockIdx.y * 128;
    const int bn = blockIdx.x * 128;
    const int lane = tid & 31;
    const int wid  = tid >> 5;
    const int warp_m = wid & 1;
    const int warp_n = wid >> 1;
    const int q4 = lane >> 2;
    const int r4 = lane & 3;

    // ldmatrix lane address components
    const int lrow = lane & 7;
    const int lg   = lane >> 3;                 // 0..3
    const int a_row = (lg & 1) * 8 + lrow;      // A: g0 rows0-7 k0 | g1 rows8-15 k0 | g2 rows0-7 k8 | g3 rows8-15 k8
    const int a_k   = (lg >> 1) * 8;
    const int b_row = (lg >> 1) * 8 + lrow;     // B: g0 (n,k0) | g1 (n,k8) | g2 (n+8,k0) | g3 (n+8,k8)
    const int b_k   = (lg & 1) * 8;

    float acc[4][4][4];
    #pragma unroll
    for (int mi = 0; mi < 4; mi++)
        #pragma unroll
        for (int nj = 0; nj < 4; nj++)
            #pragma unroll
            for (int r = 0; r < 4; r++) acc[mi][nj][r] = 0.f;

    auto issue_tile = [&](int s, int k0) {
        #pragma unroll
        for (int l = 0; l < 8; l++) {
            int f  = tid + l * 256;          // 0..2047
            int m  = f >> 4;                 // 0..127
            int kc = f & 15;                 // 16 chunks of 4 halves
            cp_async8(smem_u32(&As[s][m * SSTR + kc * 4]),
                      A + (size_t)(bm + m) * DMODEL + k0 + kc * 4);
        }
        #pragma unroll
        for (int l = 0; l < 8; l++) {
            int f  = tid + l * 256;
            int n  = f >> 4;
            int kc = f & 15;
            cp_async8(smem_u32(&Ws[s][n * SSTR + kc * 4]),
                      W + (size_t)(bn + n) * DMODEL + k0 + kc * 4);
        }
        asm volatile("cp.async.commit_group;\n");
    };

    issue_tile(0, 0);

    const int NITER = DMODEL / 64;   // 16
    for (int it = 0; it < NITER; it++) {
        const int s = it & 1;
        if (it + 1 < NITER) {
            issue_tile(s ^ 1, (it + 1) * 64);
            asm volatile("cp.async.wait_group 1;\n");
        } else {
            asm volatile("cp.async.wait_group 0;\n");
        }
        __syncthreads();

        const __half* Ab = &As[s][(warp_m * 64 + a_row) * SSTR + a_k];
        const __half* Wb = &Ws[s][(warp_n * 32 + b_row) * SSTR + b_k];
        #pragma unroll
        for (int c = 0; c < 4; c++) {
            unsigned a[4][4], bf[2][4];
            #pragma unroll
            for (int mi = 0; mi < 4; mi++)
                ldsm_x4(a[mi][0], a[mi][1], a[mi][2], a[mi][3],
                        Ab + (mi * 16) * SSTR + c * 16);
            #pragma unroll
            for (int njp = 0; njp < 2; njp++)
                ldsm_x4(bf[njp][0], bf[njp][1], bf[njp][2], bf[njp][3],
                        Wb + (njp * 16) * SSTR + c * 16);
            #pragma unroll
            for (int mi = 0; mi < 4; mi++)
                #pragma unroll
                for (int njp = 0; njp < 2; njp++) {
                    asm volatile(
                        "mma.sync.aligned.m16n8k16.row.col.f32.f16.f16.f32 "
                        "{%0,%1,%2,%3}, {%4,%5,%6,%7}, {%8,%9}, {%0,%1,%2,%3};"
                        : "+f"(acc[mi][2*njp][0]), "+f"(acc[mi][2*njp][1]),
                          "+f"(acc[mi][2*njp][2]), "+f"(acc[mi][2*njp][3])
                        : "r"(a[mi][0]), "r"(a[mi][1]), "r"(a[mi][2]), "r"(a[mi][3]),
                          "r"(bf[njp][0]), "r"(bf[njp][1]));
                    asm volatile(
                        "mma.sync.aligned.m16n8k16.row.col.f32.f16.f16.f32 "
                        "{%0,%1,%2,%3}, {%4,%5,%6,%7}, {%8,%9}, {%0,%1,%2,%3};"
                        : "+f"(acc[mi][2*njp+1][0]), "+f"(acc[mi][2*njp+1][1]),
                          "+f"(acc[mi][2*njp+1][2]), "+f"(acc[mi][2*njp+1][3])
                        : "r"(a[mi][0]), "r"(a[mi][1]), "r"(a[mi][2]), "r"(a[mi][3]),
                          "r"(bf[njp][2]), "r"(bf[njp][3]));
                }
        }
        __syncthreads();
    }

    if (round_out) {
        __half* Ch = (__half*)C;
        #pragma unroll
        for (int mi = 0; mi < 4; mi++) {
            int row = bm + warp_m * 64 + mi * 16 + q4;
            #pragma unroll
            for (int nj = 0; nj < 4; nj++) {
                int col = bn + warp_n * 32 + nj * 8 + r4 * 2;
                float b0 = bias[col], b1 = bias[col + 1];
                *reinterpret_cast<__half2*>(&Ch[(size_t)row * DMODEL + col]) =
                    __floats2half2_rn(acc[mi][nj][0] + b0, acc[mi][nj][1] + b1);
                *reinterpret_cast<__half2*>(&Ch[(size_t)(row + 8) * DMODEL + col]) =
                    __floats2half2_rn(acc[mi][nj][2] + b0, acc[mi][nj][3] + b1);
            }
        }
    } else {
        float* Cf = (float*)C;
        #pragma unroll
        for (int mi = 0; mi < 4; mi++) {
            int row = bm + warp_m * 64 + mi * 16 + q4;
            #pragma unroll
            for (int nj = 0; nj < 4; nj++) {
                int col = bn + warp_n * 32 + nj * 8 + r4 * 2;
                float b0 = bias[col], b1 = bias[col + 1];
                float2 v0 = make_float2(acc[mi][nj][0] + b0, acc[mi][nj][1] + b1);
                float2 v1 = make_float2(acc[mi][nj][2] + b0, acc[mi][nj][3] + b1);
                *reinterpret_cast<float2*>(&Cf[(size_t)row * DMODEL + col]) = v0;
                *reinterpret_cast<float2*>(&Cf[(size_t)(row + 8) * DMODEL + col]) = v1;
            }
        }
    }
}

// ------------- fp16 causal flash attention: 128-key loads, ldmatrix frags -------------
// CTA: 64 q-rows, 4 warps. QK C-frag == PV A-frag layout (no transpose).
__global__ __launch_bounds__(128, 3)
void attn_tc_kernel(const __half* __restrict__ Q, const __half* __restrict__ K,
                    const __half* __restrict__ Vt, __half* __restrict__ O) {
    __shared__ __half Ks[128 * SSTR];   // [key][d]  18.4KB
    __shared__ __half Vs[64 * VSTR];    // [d][key0..127]  17.4KB
    const int qt = gridDim.x - 1 - blockIdx.x;   // heavy tiles first
    const int h = blockIdx.y, b = blockIdx.z;
    const int tid = threadIdx.x;
    const int lane = tid & 31;
    const int w = tid >> 5;          // 0..3
    const int q4 = lane >> 2;
    const int r4 = lane & 3;
    const size_t base  = (size_t)b * SEQ * DMODEL + (size_t)h * HD;
    const size_t vbase = ((size_t)(b * NHEAD + h) * HD) * SEQ;

    const int row0 = qt * 64 + w * 16 + q4;

    // ldmatrix B-side lane components (same mapping as GEMM)
    const int lrow = lane & 7;
    const int lg   = lane >> 3;
    const int b_row = (lg >> 1) * 8 + lrow;
    const int b_k   = (lg & 1) * 8;

    // ---- Q fragments: 4 k16-chunks x 4 half2 regs, scale 1/8 exact ----
    unsigned qf[4][4];
    {
        const __half* Qp = Q + base + (size_t)row0 * DMODEL;
        const __half2 sc = __floats2half2_rn(0.125f, 0.125f);
        #pragma unroll
        for (int c = 0; c < 4; c++) {
            int d0 = c * 16 + r4 * 2;
            #pragma unroll
            for (int r = 0; r < 4; r++) {
                int off = d0 + ((r >> 1) ? 8 : 0) + ((r & 1) ? 8 * DMODEL : 0);
                unsigned u = ldh2(Qp + off);
                __half2 hv = *reinterpret_cast<__half2*>(&u);
                hv = __hmul2(hv, sc);
                qf[c][r] = *reinterpret_cast<unsigned*>(&hv);
            }
        }
    }

    float m0 = -1e30f, m1 = -1e30f, l0 = 0.f, l1 = 0.f;
    float oacc[8][4];
    #pragma unroll
    for (int of = 0; of < 8; of++)
        #pragma unroll
        for (int r = 0; r < 4; r++) oacc[of][r] = 0.f;

    const int n64 = qt + 1;                 // # of 64-key tiles
    const int nt  = (n64 + 1) >> 1;         // # of 128-key loads (nt*128 <= 2048 always)
    for (int t = 0; t < nt; t++) {
        __syncthreads();
        // ---- load 128 keys of K [key][d] and Vt [d][key] ----
        const __half* Kp = K + base + (size_t)(t * 128) * DMODEL;
        const __half* Vp = Vt + vbase + t * 128;
        #pragma unroll
        for (int l = 0; l < 8; l++) {
            int f = tid + l * 128;          // 0..1023
            int n = f >> 3, dc = f & 7;
            *reinterpret_cast<float4*>(&Ks[n * SSTR + dc * 8]) =
                *reinterpret_cast<const float4*>(Kp + (size_t)n * DMODEL + dc * 8);
        }
        #pragma unroll
        for (int l = 0; l < 8; l++) {
            int f = tid + l * 128;          // 0..1023
            int d = f >> 4, sc2 = f & 15;
            *reinterpret_cast<float4*>(&Vs[d * VSTR + sc2 * 8]) =
                *reinterpret_cast<const float4*>(Vp + (size_t)d * SEQ + sc2 * 8);
        }
        __syncthreads();

        #pragma unroll
        for (int h2 = 0; h2 < 2; h2++) {
            const int j = 2 * t + h2;
            if (j > qt) break;
            const __half* Kb = &Ks[(h2 * 64 + b_row) * SSTR + b_k];
            const __half* Vb = &Vs[b_row * VSTR + h2 * 64 + b_k];

            // ---- S = (Q/8) K^T : ldmatrix B frags (2 nf per x4) ----
            float sacc[8][4];
            #pragma unroll
            for (int nf = 0; nf < 8; nf++)
                #pragma unroll
                for (int r = 0; r < 4; r++) sacc[nf][r] = 0.f;

            #pragma unroll
            for (int c = 0; c < 4; c++) {
                #pragma unroll
                for (int np = 0; np < 4; np++) {
                    unsigned bf0, bf1, bf2, bf3;
                    ldsm_x4(bf0, bf1, bf2, bf3, Kb + (np * 16) * SSTR + c * 16);
                    asm volatile(
                        "mma.sync.aligned.m16n8k16.row.col.f32.f16.f16.f32 "
                        "{%0,%1,%2,%3}, {%4,%5,%6,%7}, {%8,%9}, {%0,%1,%2,%3};"
                        : "+f"(sacc[2*np][0]), "+f"(sacc[2*np][1]),
                          "+f"(sacc[2*np][2]), "+f"(sacc[2*np][3])
                        : "r"(qf[c][0]), "r"(qf[c][1]), "r"(qf[c][2]), "r"(qf[c][3]),
                          "r"(bf0), "r"(bf1));
                    asm volatile(
                        "mma.sync.aligned.m16n8k16.row.col.f32.f16.f16.f32 "
                        "{%0,%1,%2,%3}, {%4,%5,%6,%7}, {%8,%9}, {%0,%1,%2,%3};"
                        : "+f"(sacc[2*np+1][0]), "+f"(sacc[2*np+1][1]),
                          "+f"(sacc[2*np+1][2]), "+f"(sacc[2*np+1][3])
                        : "r"(qf[c][0]), "r"(qf[c][1]), "r"(qf[c][2]), "r"(qf[c][3]),
                          "r"(bf2), "r"(bf3));
                }
            }

            // ---- causal mask (diagonal tile only) ----
            if (j == qt) {
                int gcol0 = j * 64 + r4 * 2;
                #pragma unroll
                for (int nf = 0; nf < 8; nf++) {
                    int cix = gcol0 + nf * 8;
                    if (cix     > row0)     sacc[nf][0] = -1e30f;
                    if (cix + 1 > row0)     sacc[nf][1] = -1e30f;
                    if (cix     > row0 + 8) sacc[nf][2] = -1e30f;
                    if (cix + 1 > row0 + 8) sacc[nf][3] = -1e30f;
                }
            }

            // ---- online softmax (rows row0 / row0+8) ----
            float rmax0 = -1e30f, rmax1 = -1e30f;
            #pragma unroll
            for (int nf = 0; nf < 8; nf++) {
                rmax0 = fmaxf(rmax0, fmaxf(sacc[nf][0], sacc[nf][1]));
                rmax1 = fmaxf(rmax1, fmaxf(sacc[nf][2], sacc[nf][3]));
            }
            rmax0 = fmaxf(rmax0, __shfl_xor_sync(0xffffffffu, rmax0, 1));
            rmax0 = fmaxf(rmax0, __shfl_xor_sync(0xffffffffu, rmax0, 2));
            rmax1 = fmaxf(rmax1, __shfl_xor_sync(0xffffffffu, rmax1, 1));
            rmax1 = fmaxf(rmax1, __shfl_xor_sync(0xffffffffu, rmax1, 2));
            float mn0 = fmaxf(m0, rmax0), mn1 = fmaxf(m1, rmax1);
            float al0 = __expf(m0 - mn0), al1 = __expf(m1 - mn1);
            m0 = mn0; m1 = mn1;
            float rs0 = 0.f, rs1 = 0.f;
            #pragma unroll
            for (int nf = 0; nf < 8; nf++) {
                sacc[nf][0] = __expf(sacc[nf][0] - mn0);
                sacc[nf][1] = __expf(sacc[nf][1] - mn0);
                sacc[nf][2] = __expf(sacc[nf][2] - mn1);
                sacc[nf][3] = __expf(sacc[nf][3] - mn1);
                rs0 += sacc[nf][0] + sacc[nf][1];
                rs1 += sacc[nf][2] + sacc[nf][3];
            }
            rs0 += __shfl_xor_sync(0xffffffffu, rs0, 1);
            rs0 += __shfl_xor_sync(0xffffffffu, rs0, 2);
            rs1 += __shfl_xor_sync(0xffffffffu, rs1, 1);
            rs1 += __shfl_xor_sync(0xffffffffu, rs1, 2);
            l0 = l0 * al0 + rs0;
            l1 = l1 * al1 + rs1;
            #pragma unroll
            for (int of = 0; of < 8; of++) {
                oacc[of][0] *= al0; oacc[of][1] *= al0;
                oacc[of][2] *= al1; oacc[of][3] *= al1;
            }

            // ---- O += P @ V : C-frag == A-frag; ldmatrix V (2 of per x4) ----
            #pragma unroll
            for (int c = 0; c < 4; c++) {
                unsigned a0 = packh2(sacc[2 * c][0],     sacc[2 * c][1]);
                unsigned a1 = packh2(sacc[2 * c][2],     sacc[2 * c][3]);
                unsigned a2 = packh2(sacc[2 * c + 1][0], sacc[2 * c + 1][1]);
                unsigned a3 = packh2(sacc[2 * c + 1][2], sacc[2 * c + 1][3]);
                #pragma unroll
                for (int op = 0; op < 4; op++) {
                    unsigned bf0, bf1, bf2, bf3;
                    ldsm_x4(bf0, bf1, bf2, bf3, Vb + (op * 16) * VSTR + c * 16);
                    asm volatile(
                        "mma.sync.aligned.m16n8k16.row.col.f32.f16.f16.f32 "
                        "{%0,%1,%2,%3}, {%4,%5,%6,%7}, {%8,%9}, {%0,%1,%2,%3};"
                        : "+f"(oacc[2*op][0]), "+f"(oacc[2*op][1]),
                          "+f"(oacc[2*op][2]), "+f"(oacc[2*op][3])
                        : "r"(a0), "r"(a1), "r"(a2), "r"(a3),
                          "r"(bf0), "r"(bf1));
                    asm volatile(
                        "mma.sync.aligned.m16n8k16.row.col.f32.f16.f16.f32 "
                        "{%0,%1,%2,%3}, {%4,%5,%6,%7}, {%8,%9}, {%0,%1,%2,%3};"
                        : "+f"(oacc[2*op+1][0]), "+f"(oacc[2*op+1][1]),
                          "+f"(oacc[2*op+1][2]), "+f"(oacc[2*op+1][3])
                        : "r"(a0), "r"(a1), "r"(a2), "r"(a3),
                          "r"(bf2), "r"(bf3));
                }
            }
        }
    }

    // ---- epilogue: fp16 out for the Wo GEMM ----
    float inv0 = 1.0f / l0, inv1 = 1.0f / l1;
    #pragma unroll
    for (int of = 0; of < 8; of++) {
        int col = of * 8 + r4 * 2;
        *reinterpret_cast<__half2*>(&O[base + (size_t)row0 * DMODEL + col]) =
            __floats2half2_rn(oacc[of][0] * inv0, oacc[of][1] * inv0);
        *reinterpret_cast<__half2*>(&O[base + (size_t)(row0 + 8) * DMODEL + col]) =
            __floats2half2_rn(oacc[of][2] * inv1, oacc[of][3] * inv1);
    }
}

extern "C" void kernel_launch(void* const* d_in, const int* in_sizes, int n_in,
                              void* d_out, int out_size) {
    (void)in_sizes; (void)n_in; (void)out_size;
    const float* x     = (const float*)d_in[0];
    const float* Wq    = (const float*)d_in[1];
    const float* bq    = (const float*)d_in[2];
    const float* Wk    = (const float*)d_in[3];
    const float* bk    = (const float*)d_in[4];
    const float* Wv    = (const float*)d_in[5];
    const float* bv    = (const float*)d_in[6];
    const float* Wo    = (const float*)d_in[7];
    const float* bo    = (const float*)d_in[8];
    const float* gamma = (const float*)d_in[9];
    const float* beta  = (const float*)d_in[10];
    float* out = (float*)d_out;

    __half *h, *q, *k, *v, *vT, *attn, *wq, *wk, *wv, *wo;
    cudaGetSymbolAddress((void**)&h,    g_h);
    cudaGetSymbolAddress((void**)&q,    g_q);
    cudaGetSymbolAddress((void**)&k,    g_k);
    cudaGetSymbolAddress((void**)&v,    g_v);
    cudaGetSymbolAddress((void**)&vT,   g_vT);
    cudaGetSymbolAddress((void**)&attn, g_attn);
    cudaGetSymbolAddress((void**)&wq,   g_wq);
    cudaGetSymbolAddress((void**)&wk,   g_wk);
    cudaGetSymbolAddress((void**)&wv,   g_wv);
    cudaGetSymbolAddress((void**)&wo,   g_wo);

    // weights: fp32 -> fp16 + transpose to [n][k]
    wt_kernel<<<dim3(32, 32, 4), dim3(32, 8)>>>(Wq, wq, Wk, wk, Wv, wv, Wo, wo);

    ln_kernel<<<MROWS / 8, 256>>>(x, gamma, beta, h);

    // fused QKV projection (fp16 out)
    dim3 gqkv(DMODEL / 128, MROWS / 128, 3);
    gemm_bias_kernel<<<gqkv, 256>>>(h, wq, bq, q, wk, bk, k, wv, bv, v, 1);

    // V -> [b][h][d][s]
    vtrans_kernel<<<dim3(SEQ / 64, NHEAD, BATCH), 256>>>(v, vT);

    attn_tc_kernel<<<dim3(SEQ / 64, NHEAD, BATCH), 128>>>(q, k, vT, attn);

    dim3 go(DMODEL / 128, MROWS / 128, 1);
    gemm_bias_kernel<<<go, 256>>>(attn, wo, bo, out, wo, bo, out, wo, bo, out, 0);
}